// round 1
// baseline (speedup 1.0000x reference)
#include <cuda_runtime.h>
#include <cuda_bf16.h>
#include <math.h>
#include <stdint.h>

// Problem constants
#define BB 8
#define NN 512
#define DD 512
#define HH_ 8      // half heads
#define DH_ 32
#define DEG_ 16
#define EE 65536   // B*N*DEG
#define ROWS 4096  // B*N
#define SCALE 0.17677669529663687f  // 1/sqrt(32)
#define LOG2F_ 0.6931471805599453f

// ---------------- scratch (device globals; no allocs allowed) ----------------
__device__ float g_q[ROWS * DD];
__device__ float g_k[ROWS * DD];
__device__ float g_v[ROWS * DD];
__device__ float g_ctx[ROWS * DD];
__device__ float g_P[ROWS * DD];
__device__ float g_Q[ROWS * DD];
__device__ float g_ef1[(size_t)EE * DD];
__device__ float g_ef[(size_t)EE * (DD / 2)];
__device__ float g_eu[(size_t)EE * DD];

__device__ __forceinline__ float softplusf(float x) {
    return fmaxf(x, 0.f) + log1pf(expf(-fabsf(x)));
}

// ---------------- tiled SGEMM: C = A(MxK) @ W(KxN) + bias, optional softplus ----------------
// BM=BN=128, BK=8, 256 threads, 8x8 per thread. All dims divisible (M%128==0, N%128==0, K%8==0).
template <int EPI>
__global__ __launch_bounds__(256) void gemm_bias(
    const float* __restrict__ A, const float* __restrict__ W,
    const float* __restrict__ bias, float* __restrict__ C,
    int M, int N, int K)
{
    __shared__ float As[8][128];
    __shared__ float Ws[8][128];

    const int t = threadIdx.x;
    const int tx = t & 15;       // 0..15 -> col group
    const int ty = t >> 4;       // 0..15 -> row group
    const int bm = blockIdx.y * 128;
    const int bn = blockIdx.x * 128;

    const int arow = t >> 1;          // 0..127
    const int acol = (t & 1) * 4;     // 0 or 4
    const int wrow = t >> 5;          // 0..7
    const int wcol = (t & 31) * 4;    // 0..124

    const float* Ap = A + (size_t)(bm + arow) * K + acol;
    const float* Wp = W + (size_t)wrow * N + bn + wcol;

    float acc[8][8];
#pragma unroll
    for (int i = 0; i < 8; i++)
#pragma unroll
        for (int j = 0; j < 8; j++) acc[i][j] = 0.f;

    for (int kt = 0; kt < K; kt += 8) {
        float4 av = *(const float4*)(Ap + kt);
        float4 wv = *(const float4*)(Wp + (size_t)kt * N);
        __syncthreads();
        As[acol + 0][arow] = av.x;
        As[acol + 1][arow] = av.y;
        As[acol + 2][arow] = av.z;
        As[acol + 3][arow] = av.w;
        *(float4*)&Ws[wrow][wcol] = wv;
        __syncthreads();
#pragma unroll
        for (int k = 0; k < 8; k++) {
            float a[8], b[8];
            *(float4*)(a)     = *(const float4*)&As[k][ty * 8];
            *(float4*)(a + 4) = *(const float4*)&As[k][ty * 8 + 4];
            *(float4*)(b)     = *(const float4*)&Ws[k][tx * 8];
            *(float4*)(b + 4) = *(const float4*)&Ws[k][tx * 8 + 4];
#pragma unroll
            for (int i = 0; i < 8; i++)
#pragma unroll
                for (int j = 0; j < 8; j++) acc[i][j] = fmaf(a[i], b[j], acc[i][j]);
        }
    }

    // epilogue
    float bvals[8];
#pragma unroll
    for (int j = 0; j < 8; j++)
        bvals[j] = bias ? bias[bn + tx * 8 + j] : 0.f;

#pragma unroll
    for (int i = 0; i < 8; i++) {
        const int row = bm + ty * 8 + i;
        float o[8];
#pragma unroll
        for (int j = 0; j < 8; j++) {
            float vv = acc[i][j] + bvals[j];
            if (EPI == 1) vv = softplusf(vv) - LOG2F_;
            o[j] = vv;
        }
        float* cp = C + (size_t)row * N + bn + tx * 8;
        *(float4*)(cp)     = *(float4*)(o);
        *(float4*)(cp + 4) = *(float4*)(o + 4);
    }
}

// ---------------- local attention: one block per (b,i) ----------------
// scores[d][h] = scale * sum_c q[bi, 256+h*32+c] * k[bj, 256+h*32+c] * ef[e, h*32+c]
// softmax over d (validity s > -10000), ctx[bi, h*64+32+c] = sum_d w * v[bj, 256+h*32+c]
__global__ __launch_bounds__(256) void local_attn(
    const float* __restrict__ q, const float* __restrict__ k,
    const float* __restrict__ v, const float* __restrict__ ef,
    const int* __restrict__ pair_j, float* __restrict__ ctx)
{
    const int bi = blockIdx.x;          // b*N + i
    const int b = bi >> 9;
    const int t = threadIdx.x;

    __shared__ float qs[256];
    __shared__ int js[16];
    __shared__ float sc[16][8];
    __shared__ float wgt[16][8];

    if (t < 16) js[t] = pair_j[bi * 16 + t];
    qs[t] = q[(size_t)bi * DD + 256 + t];
    __syncthreads();

    if (t < 128) {
        const int d = t >> 3, h = t & 7;
        const int j = js[d];
        const float* kr = k + ((size_t)(b * NN + j)) * DD + 256 + h * 32;
        const float* er = ef + ((size_t)(bi * 16 + d)) * 256 + h * 32;
        const float* qr = qs + h * 32;
        float s = 0.f;
#pragma unroll
        for (int c4 = 0; c4 < 8; c4++) {
            float4 kk = *(const float4*)(kr + c4 * 4);
            float4 eee = *(const float4*)(er + c4 * 4);
            s = fmaf(qr[c4 * 4 + 0], kk.x * eee.x, s);
            s = fmaf(qr[c4 * 4 + 1], kk.y * eee.y, s);
            s = fmaf(qr[c4 * 4 + 2], kk.z * eee.z, s);
            s = fmaf(qr[c4 * 4 + 3], kk.w * eee.w, s);
        }
        sc[d][h] = s * SCALE;
    }
    __syncthreads();

    if (t < 8) {
        const int h = t;
        float m = -1e30f;
#pragma unroll
        for (int d = 0; d < 16; d++) {
            float s = sc[d][h];
            if (s > -10000.f && s > m) m = s;
        }
        float sum = 0.f;
#pragma unroll
        for (int d = 0; d < 16; d++) {
            float s = sc[d][h];
            float e = (s > -10000.f) ? expf(s - m) : 0.f;
            wgt[d][h] = e;
            sum += e;
        }
        float inv = (sum > 0.f) ? 1.f / sum : 0.f;
#pragma unroll
        for (int d = 0; d < 16; d++) wgt[d][h] *= inv;
    }
    __syncthreads();

    const int h = t >> 5, c = t & 31;
    float o = 0.f;
#pragma unroll
    for (int d = 0; d < 16; d++) {
        float w = wgt[d][h];
        o = fmaf(w, v[((size_t)(b * NN + js[d])) * DD + 256 + h * 32 + c], o);
    }
    ctx[(size_t)bi * DD + h * 64 + 32 + c] = o;
}

// ---------------- global attention: block = (b, h, tile of 8 i) ----------------
__global__ __launch_bounds__(256) void global_attn(
    const float* __restrict__ q, const float* __restrict__ k,
    const float* __restrict__ v, const unsigned char* __restrict__ mask,
    float* __restrict__ ctx, float* __restrict__ top)
{
    const int b = blockIdx.z, h = blockIdx.y, it = blockIdx.x; // i0 = it*8
    const int t = threadIdx.x;

    __shared__ float Qs[8][32];
    __shared__ float Ks[64][32];
    __shared__ float S[8][512];

    {
        const int i = t >> 5, c = t & 31;
        Qs[i][c] = q[((size_t)(b * NN) + it * 8 + i) * DD + h * 32 + c] * SCALE;
    }

    const int lrow = t >> 2, lseg = (t & 3) * 8;

    // --- scores ---
    for (int jt = 0; jt < 8; jt++) {
        const float* kr = k + ((size_t)(b * NN) + jt * 64 + lrow) * DD + h * 32 + lseg;
        float4 k0 = *(const float4*)kr;
        float4 k1 = *(const float4*)(kr + 4);
        __syncthreads();
        *(float4*)&Ks[lrow][lseg] = k0;
        *(float4*)&Ks[lrow][lseg + 4] = k1;
        __syncthreads();
#pragma unroll
        for (int r = 0; r < 2; r++) {
            const int idx = t + 256 * r;
            const int i = idx & 7, jl = idx >> 3;
            float s = 0.f;
#pragma unroll
            for (int c = 0; c < 32; c++) s = fmaf(Qs[i][c], Ks[jl][c], s);
            S[i][jt * 64 + jl] = s;
        }
    }
    __syncthreads();

    // --- top_score (head 0, pre-mask) ---
    if (h == 0) {
#pragma unroll
        for (int r = 0; r < 16; r++) {
            const int idx = t + 256 * r;
            const int i = idx >> 9, j = idx & 511;
            top[((size_t)(b * NN) + it * 8 + i) * NN + j] = S[i][j];
        }
    }
    // --- mask ---
#pragma unroll
    for (int r = 0; r < 16; r++) {
        const int idx = t + 256 * r;
        const int i = idx >> 9, j = idx & 511;
        if (mask[((size_t)(b * NN) + it * 8 + i) * NN + j]) S[i][j] = -1e18f;
    }
    __syncthreads();

    // --- softmax per i (warp w handles row w) ---
    {
        const int i = t >> 5, lane = t & 31;
        float m = -1e30f;
        for (int j = lane; j < 512; j += 32) m = fmaxf(m, S[i][j]);
#pragma unroll
        for (int o = 16; o; o >>= 1) m = fmaxf(m, __shfl_xor_sync(0xffffffffu, m, o));
        float sum = 0.f;
        for (int j = lane; j < 512; j += 32) {
            float e = __expf(S[i][j] - m);
            S[i][j] = e;
            sum += e;
        }
#pragma unroll
        for (int o = 16; o; o >>= 1) sum += __shfl_xor_sync(0xffffffffu, sum, o);
        float inv = 1.f / sum;
        for (int j = lane; j < 512; j += 32) S[i][j] *= inv;
    }
    __syncthreads();

    // --- ctx: reuse Ks for V tiles ---
    const int i = t >> 5, c = t & 31;
    float acc = 0.f;
    for (int jt = 0; jt < 8; jt++) {
        const float* vr = v + ((size_t)(b * NN) + jt * 64 + lrow) * DD + h * 32 + lseg;
        float4 v0 = *(const float4*)vr;
        float4 v1 = *(const float4*)(vr + 4);
        __syncthreads();
        *(float4*)&Ks[lrow][lseg] = v0;
        *(float4*)&Ks[lrow][lseg + 4] = v1;
        __syncthreads();
#pragma unroll
        for (int jl = 0; jl < 64; jl++) acc = fmaf(S[i][jt * 64 + jl], Ks[jl][c], acc);
    }
    ctx[((size_t)(b * NN) + it * 8 + i) * DD + h * 64 + c] = acc;
}

// ---------------- eu = softplus(P[row_i] + Q[row_j]) - log2 ----------------
__global__ __launch_bounds__(128) void eu_kernel(
    const float* __restrict__ P, const float* __restrict__ Q,
    const int* __restrict__ pair_b, const int* __restrict__ pair_i,
    const int* __restrict__ pair_j, float* __restrict__ eu)
{
    const int e = blockIdx.x;
    const int b = pair_b[e], i = pair_i[e], j = pair_j[e];
    const float4* pr = (const float4*)(P + ((size_t)(b * NN + i)) * DD);
    const float4* qr = (const float4*)(Q + ((size_t)(b * NN + j)) * DD);
    float4* o = (float4*)(eu + (size_t)e * DD);
    const int t = threadIdx.x;  // 128 threads, 4 floats each = 512
    float4 a = pr[t], c = qr[t];
    float4 r;
    r.x = softplusf(a.x + c.x) - LOG2F_;
    r.y = softplusf(a.y + c.y) - LOG2F_;
    r.z = softplusf(a.z + c.z) - LOG2F_;
    r.w = softplusf(a.w + c.w) - LOG2F_;
    o[t] = r;
}

// ---------------- launch ----------------
extern "C" void kernel_launch(void* const* d_in, const int* in_sizes, int n_in,
                              void* d_out, int out_size)
{
    const float* key    = (const float*)d_in[0];
    const float* value  = (const float*)d_in[1];
    const float* query  = (const float*)d_in[2];
    const unsigned char* mask = (const unsigned char*)d_in[3];
    const float* edgef  = (const float*)d_in[4];
    const int* pair_b   = (const int*)d_in[5];
    const int* pair_i   = (const int*)d_in[6];
    const int* pair_j   = (const int*)d_in[7];
    const float* Wq = (const float*)d_in[8],  *bq = (const float*)d_in[9];
    const float* Wk = (const float*)d_in[10], *bk = (const float*)d_in[11];
    const float* Wv = (const float*)d_in[12], *bv = (const float*)d_in[13];
    const float* Wo = (const float*)d_in[14], *bo = (const float*)d_in[15];
    const float* We1 = (const float*)d_in[16], *be1 = (const float*)d_in[17];
    const float* We2 = (const float*)d_in[18], *be2 = (const float*)d_in[19];
    const float* Wu1 = (const float*)d_in[20], *bu1 = (const float*)d_in[21];
    const float* Wu2 = (const float*)d_in[22], *bu2 = (const float*)d_in[23];

    float* out  = (float*)d_out;                 // [B,N,D]     2,097,152
    float* top  = out + 2097152;                 // [B,N,N]     2,097,152
    float* eupd = out + 4194304;                 // [E,D]      33,554,432

    float *q_, *k_, *v_, *ctx_, *P_, *Q_, *ef1_, *ef_, *eu_;
    cudaGetSymbolAddress((void**)&q_, g_q);
    cudaGetSymbolAddress((void**)&k_, g_k);
    cudaGetSymbolAddress((void**)&v_, g_v);
    cudaGetSymbolAddress((void**)&ctx_, g_ctx);
    cudaGetSymbolAddress((void**)&P_, g_P);
    cudaGetSymbolAddress((void**)&Q_, g_Q);
    cudaGetSymbolAddress((void**)&ef1_, g_ef1);
    cudaGetSymbolAddress((void**)&ef_, g_ef);
    cudaGetSymbolAddress((void**)&eu_, g_eu);

    // projections
    gemm_bias<0><<<dim3(4, 32), 256>>>(key,   Wk, bk, k_, ROWS, 512, 512);
    gemm_bias<0><<<dim3(4, 32), 256>>>(query, Wq, bq, q_, ROWS, 512, 512);
    gemm_bias<0><<<dim3(4, 32), 256>>>(value, Wv, bv, v_, ROWS, 512, 512);

    // edge feature MLP
    gemm_bias<1><<<dim3(4, 512), 256>>>(edgef, We1, be1, ef1_, EE, 512, 512);
    gemm_bias<0><<<dim3(2, 512), 256>>>(ef1_,  We2, be2, ef_,  EE, 256, 512);

    // attention -> ctx
    local_attn<<<ROWS, 256>>>(q_, k_, v_, ef_, pair_j, ctx_);
    global_attn<<<dim3(64, 8, 8), 256>>>(q_, k_, v_, mask, ctx_, top);

    // output projection
    gemm_bias<0><<<dim3(4, 32), 256>>>(ctx_, Wo, bo, out, ROWS, 512, 512);

    // nf@Wu1 factored: P = out@Wu1_top + bu1 ; Q = out@Wu1_bot
    gemm_bias<0><<<dim3(4, 32), 256>>>(out, Wu1,           bu1,     P_, ROWS, 512, 512);
    gemm_bias<0><<<dim3(4, 32), 256>>>(out, Wu1 + 262144,  nullptr, Q_, ROWS, 512, 512);

    // eu = softplus(P_i + Q_j) - log2
    eu_kernel<<<EE, 128>>>(P_, Q_, pair_b, pair_i, pair_j, eu_);

    // edge_updated = eu @ Wu2 + bu2
    gemm_bias<0><<<dim3(4, 512), 256>>>(eu_, Wu2, bu2, eupd, EE, 512, 512);
}

// round 3
// speedup vs baseline: 1.8794x; 1.8794x over previous
#include <cuda_runtime.h>
#include <cuda_bf16.h>
#include <math.h>
#include <stdint.h>

// Problem constants
#define BB 8
#define NN 512
#define DD 512
#define DEG_ 16
#define EE 65536   // B*N*DEG
#define ROWS 4096  // B*N
#define GK 512     // K dim of all big GEMMs
#define SCALE 0.17677669529663687f  // 1/sqrt(32)
#define LOG2F_ 0.6931471805599453f

// ---------------- scratch (device globals; no allocs allowed) ----------------
__device__ float g_q[ROWS * DD];
__device__ float g_k[ROWS * DD];
__device__ float g_v[ROWS * DD];
__device__ float g_ctx[ROWS * DD];
__device__ float g_P[ROWS * DD];
__device__ float g_Q[ROWS * DD];
__device__ float g_ef[(size_t)EE * 256];

__device__ __nv_bfloat16 g_eHi[(size_t)EE * DD];
__device__ __nv_bfloat16 g_eLo[(size_t)EE * DD];
__device__ __nv_bfloat16 g_f1Hi[(size_t)EE * DD];
__device__ __nv_bfloat16 g_f1Lo[(size_t)EE * DD];
__device__ __nv_bfloat16 g_euHi[(size_t)EE * DD];
__device__ __nv_bfloat16 g_euLo[(size_t)EE * DD];

__device__ __nv_bfloat16 g_xHi[ROWS * DD];   // input split scratch (reused)
__device__ __nv_bfloat16 g_xLo[ROWS * DD];
__device__ __nv_bfloat16 g_oHi[ROWS * DD];   // output proj hi/lo
__device__ __nv_bfloat16 g_oLo[ROWS * DD];

// weights: 0 Wk,1 Wq,2 Wv,3 Wo,4 Wu1a,5 Wu1b,6 Wu2,7 We1, 8 We2(256x512)
__device__ __nv_bfloat16 g_WHi[9 * 262144];
__device__ __nv_bfloat16 g_WLo[9 * 262144];

__device__ __forceinline__ float softplusf(float x) {
    return fmaxf(x, 0.f) + log1pf(expf(-fabsf(x)));
}

__device__ __forceinline__ uint32_t smem_to_u32(const void* smem_ptr) {
    uint32_t addr;
    asm("{ .reg .u64 tmp; cvta.to.shared.u64 tmp, %1; cvt.u32.u64 %0, tmp; }"
        : "=r"(addr) : "l"(smem_ptr));
    return addr;
}

// ---------------- PTX: cp.async / ldmatrix / mma (all base-arch legal) ----------------
__device__ __forceinline__ void cpasync16(uint32_t saddr, const void* g) {
    asm volatile("cp.async.cg.shared.global [%0], [%1], 16;" :: "r"(saddr), "l"(g));
}
#define CP_COMMIT() asm volatile("cp.async.commit_group;")
#define CP_WAIT(n)  asm volatile("cp.async.wait_group %0;" :: "n"(n))

__device__ __forceinline__ void ldmx4(uint32_t r[4], uint32_t addr) {
    asm volatile("ldmatrix.sync.aligned.m8n8.x4.shared.b16 {%0,%1,%2,%3}, [%4];"
                 : "=r"(r[0]), "=r"(r[1]), "=r"(r[2]), "=r"(r[3]) : "r"(addr));
}

__device__ __forceinline__ void mma16816(float c[4], const uint32_t a[4],
                                         uint32_t b0, uint32_t b1) {
    asm volatile("mma.sync.aligned.m16n8k16.row.col.f32.bf16.bf16.f32 "
                 "{%0,%1,%2,%3}, {%4,%5,%6,%7}, {%8,%9}, {%0,%1,%2,%3};"
                 : "+f"(c[0]), "+f"(c[1]), "+f"(c[2]), "+f"(c[3])
                 : "r"(a[0]), "r"(a[1]), "r"(a[2]), "r"(a[3]), "r"(b0), "r"(b1));
}

__device__ __forceinline__ void split2(float x, float y, uint32_t& hp, uint32_t& lp) {
    __nv_bfloat16 hx = __float2bfloat16(x), hy = __float2bfloat16(y);
    __nv_bfloat16 lx = __float2bfloat16(x - __bfloat162float(hx));
    __nv_bfloat16 ly = __float2bfloat16(y - __bfloat162float(hy));
    hp = ((uint32_t)__bfloat16_as_ushort(hy) << 16) | __bfloat16_as_ushort(hx);
    lp = ((uint32_t)__bfloat16_as_ushort(ly) << 16) | __bfloat16_as_ushort(lx);
}

// ======================= tensor-core GEMM (mma.sync bf16, hi/lo split) =======================
// C[M x N] = A[M x 512] @ B^T, A [M,512] hi/lo bf16, B [N,512] hi/lo bf16 (K-major).
// CTA 128x128, 8 warps of 32x64, BK=32, cp.async double buffer.
// SMEM tile layout: rows of 32 bf16 padded to 40 (80 bytes).
#define ROWB 80
#define TILE_B (128 * ROWB)      // 10240
#define AH_OFF 0
#define AL_OFF (1 * TILE_B)
#define BH_OFF (2 * TILE_B)
#define BL_OFF (3 * TILE_B)
#define STAGE_B (4 * TILE_B)     // 40960
#define TC_SMEM (2 * STAGE_B)    // 81920

__device__ __forceinline__ void load_stage(
    uint32_t sbase,
    const __nv_bfloat16* __restrict__ Ahi, const __nv_bfloat16* __restrict__ Alo,
    const __nv_bfloat16* __restrict__ Bhi, const __nv_bfloat16* __restrict__ Blo,
    int bm, int bn, int kc, int t)
{
#pragma unroll
    for (int i = 0; i < 2; i++) {
        const int id = t + i * 256;           // 0..511
        const int row = id >> 2, ch = id & 3;
        const uint32_t soff = row * ROWB + ch * 16;
        const size_t gA = (size_t)(bm + row) * GK + kc * 32 + ch * 8;
        const size_t gB = (size_t)(bn + row) * GK + kc * 32 + ch * 8;
        cpasync16(sbase + AH_OFF + soff, Ahi + gA);
        cpasync16(sbase + AL_OFF + soff, Alo + gA);
        cpasync16(sbase + BH_OFF + soff, Bhi + gB);
        cpasync16(sbase + BL_OFF + soff, Blo + gB);
    }
}

// OUT: 0 = f32 only, 1 = hi/lo only, 2 = f32 + hi/lo
template <int SOFTPLUS, int OUT>
__global__ __launch_bounds__(256) void tc_gemm(
    const __nv_bfloat16* __restrict__ Ahi, const __nv_bfloat16* __restrict__ Alo,
    const __nv_bfloat16* __restrict__ Bhi, const __nv_bfloat16* __restrict__ Blo,
    const float* __restrict__ bias,
    float* __restrict__ Cf, __nv_bfloat16* __restrict__ Chi, __nv_bfloat16* __restrict__ Clo,
    int N)
{
    extern __shared__ char smem[];
    const uint32_t sb = smem_to_u32(smem);
    const int t = threadIdx.x, lane = t & 31, w = t >> 5;
    const int wm = w & 3, wn = w >> 2;
    const int bm = blockIdx.y * 128, bn = blockIdx.x * 128;

    float acc[2][8][4] = {};

    // per-thread ldmatrix offsets
    const uint32_t aRow = (uint32_t)(wm * 32 + (lane & 15)) * ROWB + ((lane >> 4) << 4);
    const int n_off = (lane & 7) + ((lane >> 4) << 3);
    const int k_half = (lane >> 3) & 1;
    const uint32_t bRow = (uint32_t)(wn * 64 + n_off) * ROWB + (k_half << 4);

    load_stage(sb, Ahi, Alo, Bhi, Blo, bm, bn, 0, t);
    CP_COMMIT();

    for (int kc = 0; kc < GK / 32; kc++) {
        const uint32_t cur = sb + (kc & 1) * STAGE_B;
        if (kc < GK / 32 - 1) {
            load_stage(sb + ((kc + 1) & 1) * STAGE_B, Ahi, Alo, Bhi, Blo, bm, bn, kc + 1, t);
            CP_COMMIT();
            CP_WAIT(1);
        } else {
            CP_WAIT(0);
        }
        __syncthreads();

#pragma unroll
        for (int ks = 0; ks < 2; ks++) {
            const uint32_t kb = ks * 32;
            uint32_t ah[2][4], al[2][4], bh[4][4], bl[4][4];
            ldmx4(ah[0], cur + AH_OFF + aRow + kb);
            ldmx4(ah[1], cur + AH_OFF + aRow + 16 * ROWB + kb);
            ldmx4(al[0], cur + AL_OFF + aRow + kb);
            ldmx4(al[1], cur + AL_OFF + aRow + 16 * ROWB + kb);
#pragma unroll
            for (int jj = 0; jj < 4; jj++) {
                ldmx4(bh[jj], cur + BH_OFF + bRow + jj * 16 * ROWB + kb);
                ldmx4(bl[jj], cur + BL_OFF + bRow + jj * 16 * ROWB + kb);
            }
#pragma unroll
            for (int g = 0; g < 2; g++) {
#pragma unroll
                for (int j = 0; j < 8; j++) {
                    const int jj = j >> 1, hf = (j & 1) * 2;
                    mma16816(acc[g][j], ah[g], bh[jj][hf], bh[jj][hf + 1]);
                    mma16816(acc[g][j], ah[g], bl[jj][hf], bl[jj][hf + 1]);
                    mma16816(acc[g][j], al[g], bh[jj][hf], bh[jj][hf + 1]);
                }
            }
        }
        __syncthreads();
    }

    // epilogue
#pragma unroll
    for (int g = 0; g < 2; g++) {
#pragma unroll
        for (int j = 0; j < 8; j++) {
            const int row = bm + wm * 32 + g * 16 + (lane >> 2);
            const int col = bn + wn * 64 + j * 8 + (lane & 3) * 2;
            float b0 = bias ? bias[col] : 0.f;
            float b1 = bias ? bias[col + 1] : 0.f;
            float v0 = acc[g][j][0] + b0, v1 = acc[g][j][1] + b1;
            float v2 = acc[g][j][2] + b0, v3 = acc[g][j][3] + b1;
            if (SOFTPLUS) {
                v0 = softplusf(v0) - LOG2F_; v1 = softplusf(v1) - LOG2F_;
                v2 = softplusf(v2) - LOG2F_; v3 = softplusf(v3) - LOG2F_;
            }
            if (OUT == 0 || OUT == 2) {
                *(float2*)(Cf + (size_t)row * N + col) = make_float2(v0, v1);
                *(float2*)(Cf + (size_t)(row + 8) * N + col) = make_float2(v2, v3);
            }
            if (OUT == 1 || OUT == 2) {
                uint32_t hp, lp;
                split2(v0, v1, hp, lp);
                *(uint32_t*)(Chi + (size_t)row * N + col) = hp;
                *(uint32_t*)(Clo + (size_t)row * N + col) = lp;
                split2(v2, v3, hp, lp);
                *(uint32_t*)(Chi + (size_t)(row + 8) * N + col) = hp;
                *(uint32_t*)(Clo + (size_t)(row + 8) * N + col) = lp;
            }
        }
    }
}

// ---------------- fp32 -> bf16 hi/lo split (vectorized) ----------------
__global__ __launch_bounds__(256) void conv_hilo(
    const float* __restrict__ x, __nv_bfloat16* __restrict__ hi,
    __nv_bfloat16* __restrict__ lo, size_t n4)
{
    size_t i = (size_t)blockIdx.x * 256 + threadIdx.x;
    if (i >= n4) return;
    float4 v = ((const float4*)x)[i];
    uint2 uh, ul;
    split2(v.x, v.y, uh.x, ul.x);
    split2(v.z, v.w, uh.y, ul.y);
    *(uint2*)(hi + i * 4) = uh;
    *(uint2*)(lo + i * 4) = ul;
}

// ---------------- weight transpose + hi/lo: W[K,N] -> Wt[N,K] ----------------
__global__ __launch_bounds__(256) void wconv(
    const float* __restrict__ W, __nv_bfloat16* __restrict__ hi,
    __nv_bfloat16* __restrict__ lo, int Kdim, int Ndim)
{
    int idx = blockIdx.x * 256 + threadIdx.x;
    if (idx >= Kdim * Ndim) return;
    int k = idx / Ndim, n = idx % Ndim;
    float v = W[idx];
    __nv_bfloat16 h = __float2bfloat16(v);
    hi[(size_t)n * Kdim + k] = h;
    lo[(size_t)n * Kdim + k] = __float2bfloat16(v - __bfloat162float(h));
}

// ---------------- local attention: one block per (b,i) ----------------
__global__ __launch_bounds__(256) void local_attn(
    const float* __restrict__ q, const float* __restrict__ k,
    const float* __restrict__ v, const float* __restrict__ ef,
    const int* __restrict__ pair_j, float* __restrict__ ctx)
{
    const int bi = blockIdx.x;
    const int b = bi >> 9;
    const int t = threadIdx.x;

    __shared__ float qs[256];
    __shared__ int js[16];
    __shared__ float sc[16][8];
    __shared__ float wgt[16][8];

    if (t < 16) js[t] = pair_j[bi * 16 + t];
    qs[t] = q[(size_t)bi * DD + 256 + t];
    __syncthreads();

    if (t < 128) {
        const int d = t >> 3, h = t & 7;
        const int j = js[d];
        const float* kr = k + ((size_t)(b * NN + j)) * DD + 256 + h * 32;
        const float* er = ef + ((size_t)(bi * 16 + d)) * 256 + h * 32;
        const float* qr = qs + h * 32;
        float s = 0.f;
#pragma unroll
        for (int c4 = 0; c4 < 8; c4++) {
            float4 kk = *(const float4*)(kr + c4 * 4);
            float4 eee = *(const float4*)(er + c4 * 4);
            s = fmaf(qr[c4 * 4 + 0], kk.x * eee.x, s);
            s = fmaf(qr[c4 * 4 + 1], kk.y * eee.y, s);
            s = fmaf(qr[c4 * 4 + 2], kk.z * eee.z, s);
            s = fmaf(qr[c4 * 4 + 3], kk.w * eee.w, s);
        }
        sc[d][h] = s * SCALE;
    }
    __syncthreads();

    if (t < 8) {
        const int h = t;
        float m = -1e30f;
#pragma unroll
        for (int d = 0; d < 16; d++) {
            float s = sc[d][h];
            if (s > -10000.f && s > m) m = s;
        }
        float sum = 0.f;
#pragma unroll
        for (int d = 0; d < 16; d++) {
            float s = sc[d][h];
            float e = (s > -10000.f) ? expf(s - m) : 0.f;
            wgt[d][h] = e;
            sum += e;
        }
        float inv = (sum > 0.f) ? 1.f / sum : 0.f;
#pragma unroll
        for (int d = 0; d < 16; d++) wgt[d][h] *= inv;
    }
    __syncthreads();

    const int h = t >> 5, c = t & 31;
    float o = 0.f;
#pragma unroll
    for (int d = 0; d < 16; d++) {
        float w = wgt[d][h];
        o = fmaf(w, v[((size_t)(b * NN + js[d])) * DD + 256 + h * 32 + c], o);
    }
    ctx[(size_t)bi * DD + h * 64 + 32 + c] = o;
}

// ---------------- global attention: block = (b, h, tile of 8 i) ----------------
__global__ __launch_bounds__(256) void global_attn(
    const float* __restrict__ q, const float* __restrict__ k,
    const float* __restrict__ v, const unsigned char* __restrict__ mask,
    float* __restrict__ ctx, float* __restrict__ top)
{
    const int b = blockIdx.z, h = blockIdx.y, it = blockIdx.x;
    const int t = threadIdx.x;

    __shared__ float Qs[8][32];
    __shared__ float Ks[64][32];
    __shared__ float S[8][512];

    {
        const int i = t >> 5, c = t & 31;
        Qs[i][c] = q[((size_t)(b * NN) + it * 8 + i) * DD + h * 32 + c] * SCALE;
    }

    const int lrow = t >> 2, lseg = (t & 3) * 8;

    for (int jt = 0; jt < 8; jt++) {
        const float* kr = k + ((size_t)(b * NN) + jt * 64 + lrow) * DD + h * 32 + lseg;
        float4 k0 = *(const float4*)kr;
        float4 k1 = *(const float4*)(kr + 4);
        __syncthreads();
        *(float4*)&Ks[lrow][lseg] = k0;
        *(float4*)&Ks[lrow][lseg + 4] = k1;
        __syncthreads();
#pragma unroll
        for (int r = 0; r < 2; r++) {
            const int idx = t + 256 * r;
            const int i = idx & 7, jl = idx >> 3;
            float s = 0.f;
#pragma unroll
            for (int c = 0; c < 32; c++) s = fmaf(Qs[i][c], Ks[jl][c], s);
            S[i][jt * 64 + jl] = s;
        }
    }
    __syncthreads();

    if (h == 0) {
#pragma unroll
        for (int r = 0; r < 16; r++) {
            const int idx = t + 256 * r;
            const int i = idx >> 9, j = idx & 511;
            top[((size_t)(b * NN) + it * 8 + i) * NN + j] = S[i][j];
        }
    }
#pragma unroll
    for (int r = 0; r < 16; r++) {
        const int idx = t + 256 * r;
        const int i = idx >> 9, j = idx & 511;
        if (mask[((size_t)(b * NN) + it * 8 + i) * NN + j]) S[i][j] = -1e18f;
    }
    __syncthreads();

    {
        const int i = t >> 5, lane = t & 31;
        float m = -1e30f;
        for (int j = lane; j < 512; j += 32) m = fmaxf(m, S[i][j]);
#pragma unroll
        for (int o = 16; o; o >>= 1) m = fmaxf(m, __shfl_xor_sync(0xffffffffu, m, o));
        float sum = 0.f;
        for (int j = lane; j < 512; j += 32) {
            float e = __expf(S[i][j] - m);
            S[i][j] = e;
            sum += e;
        }
#pragma unroll
        for (int o = 16; o; o >>= 1) sum += __shfl_xor_sync(0xffffffffu, sum, o);
        float inv = 1.f / sum;
        for (int j = lane; j < 512; j += 32) S[i][j] *= inv;
    }
    __syncthreads();

    const int i = t >> 5, c = t & 31;
    float acc = 0.f;
    for (int jt = 0; jt < 8; jt++) {
        const float* vr = v + ((size_t)(b * NN) + jt * 64 + lrow) * DD + h * 32 + lseg;
        float4 v0 = *(const float4*)vr;
        float4 v1 = *(const float4*)(vr + 4);
        __syncthreads();
        *(float4*)&Ks[lrow][lseg] = v0;
        *(float4*)&Ks[lrow][lseg + 4] = v1;
        __syncthreads();
#pragma unroll
        for (int jl = 0; jl < 64; jl++) acc = fmaf(S[i][jt * 64 + jl], Ks[jl][c], acc);
    }
    ctx[((size_t)(b * NN) + it * 8 + i) * DD + h * 64 + c] = acc;
}

// ---------------- eu = softplus(P[row_i] + Q[row_j]) - log2  (-> bf16 hi/lo) ----------------
__global__ __launch_bounds__(128) void eu_kernel(
    const float* __restrict__ P, const float* __restrict__ Q,
    const int* __restrict__ pair_b, const int* __restrict__ pair_i,
    const int* __restrict__ pair_j,
    __nv_bfloat16* __restrict__ euHi, __nv_bfloat16* __restrict__ euLo)
{
    const int e = blockIdx.x;
    const int b = pair_b[e], i = pair_i[e], j = pair_j[e];
    const float4* pr = (const float4*)(P + ((size_t)(b * NN + i)) * DD);
    const float4* qr = (const float4*)(Q + ((size_t)(b * NN + j)) * DD);
    const int t = threadIdx.x;
    float4 a = pr[t], c = qr[t];
    float r0 = softplusf(a.x + c.x) - LOG2F_;
    float r1 = softplusf(a.y + c.y) - LOG2F_;
    float r2 = softplusf(a.z + c.z) - LOG2F_;
    float r3 = softplusf(a.w + c.w) - LOG2F_;
    uint2 uh, ul;
    split2(r0, r1, uh.x, ul.x);
    split2(r2, r3, uh.y, ul.y);
    *(uint2*)(euHi + (size_t)e * DD + t * 4) = uh;
    *(uint2*)(euLo + (size_t)e * DD + t * 4) = ul;
}

// ---------------- launch ----------------
extern "C" void kernel_launch(void* const* d_in, const int* in_sizes, int n_in,
                              void* d_out, int out_size)
{
    const float* key    = (const float*)d_in[0];
    const float* value  = (const float*)d_in[1];
    const float* query  = (const float*)d_in[2];
    const unsigned char* mask = (const unsigned char*)d_in[3];
    const float* edgef  = (const float*)d_in[4];
    const int* pair_b   = (const int*)d_in[5];
    const int* pair_i   = (const int*)d_in[6];
    const int* pair_j   = (const int*)d_in[7];
    const float* Wq = (const float*)d_in[8],  *bq = (const float*)d_in[9];
    const float* Wk = (const float*)d_in[10], *bk = (const float*)d_in[11];
    const float* Wv = (const float*)d_in[12], *bv = (const float*)d_in[13];
    const float* Wo = (const float*)d_in[14], *bo = (const float*)d_in[15];
    const float* We1 = (const float*)d_in[16], *be1 = (const float*)d_in[17];
    const float* We2 = (const float*)d_in[18], *be2 = (const float*)d_in[19];
    const float* Wu1 = (const float*)d_in[20], *bu1 = (const float*)d_in[21];
    const float* Wu2 = (const float*)d_in[22], *bu2 = (const float*)d_in[23];

    float* out  = (float*)d_out;
    float* top  = out + 2097152;
    float* eupd = out + 4194304;

    float *q_, *k_, *v_, *ctx_, *P_, *Q_, *ef_;
    __nv_bfloat16 *eHi_, *eLo_, *f1Hi_, *f1Lo_, *euHi_, *euLo_;
    __nv_bfloat16 *xHi_, *xLo_, *oHi_, *oLo_, *WHi_, *WLo_;
    cudaGetSymbolAddress((void**)&q_, g_q);
    cudaGetSymbolAddress((void**)&k_, g_k);
    cudaGetSymbolAddress((void**)&v_, g_v);
    cudaGetSymbolAddress((void**)&ctx_, g_ctx);
    cudaGetSymbolAddress((void**)&P_, g_P);
    cudaGetSymbolAddress((void**)&Q_, g_Q);
    cudaGetSymbolAddress((void**)&ef_, g_ef);
    cudaGetSymbolAddress((void**)&eHi_, g_eHi);
    cudaGetSymbolAddress((void**)&eLo_, g_eLo);
    cudaGetSymbolAddress((void**)&f1Hi_, g_f1Hi);
    cudaGetSymbolAddress((void**)&f1Lo_, g_f1Lo);
    cudaGetSymbolAddress((void**)&euHi_, g_euHi);
    cudaGetSymbolAddress((void**)&euLo_, g_euLo);
    cudaGetSymbolAddress((void**)&xHi_, g_xHi);
    cudaGetSymbolAddress((void**)&xLo_, g_xLo);
    cudaGetSymbolAddress((void**)&oHi_, g_oHi);
    cudaGetSymbolAddress((void**)&oLo_, g_oLo);
    cudaGetSymbolAddress((void**)&WHi_, g_WHi);
    cudaGetSymbolAddress((void**)&WLo_, g_WLo);

    cudaFuncSetAttribute((const void*)tc_gemm<0, 0>,
                         cudaFuncAttributeMaxDynamicSharedMemorySize, TC_SMEM);
    cudaFuncSetAttribute((const void*)tc_gemm<1, 1>,
                         cudaFuncAttributeMaxDynamicSharedMemorySize, TC_SMEM);
    cudaFuncSetAttribute((const void*)tc_gemm<0, 2>,
                         cudaFuncAttributeMaxDynamicSharedMemorySize, TC_SMEM);

    const int WSZ = 262144;
    // weight transpose + split
    wconv<<<1024, 256>>>(Wk,  WHi_ + 0 * WSZ, WLo_ + 0 * WSZ, 512, 512);
    wconv<<<1024, 256>>>(Wq,  WHi_ + 1 * WSZ, WLo_ + 1 * WSZ, 512, 512);
    wconv<<<1024, 256>>>(Wv,  WHi_ + 2 * WSZ, WLo_ + 2 * WSZ, 512, 512);
    wconv<<<1024, 256>>>(Wo,  WHi_ + 3 * WSZ, WLo_ + 3 * WSZ, 512, 512);
    wconv<<<1024, 256>>>(Wu1,           WHi_ + 4 * WSZ, WLo_ + 4 * WSZ, 512, 512);
    wconv<<<1024, 256>>>(Wu1 + 262144,  WHi_ + 5 * WSZ, WLo_ + 5 * WSZ, 512, 512);
    wconv<<<1024, 256>>>(Wu2, WHi_ + 6 * WSZ, WLo_ + 6 * WSZ, 512, 512);
    wconv<<<1024, 256>>>(We1, WHi_ + 7 * WSZ, WLo_ + 7 * WSZ, 512, 512);
    wconv<<<512,  256>>>(We2, WHi_ + 8 * WSZ, WLo_ + 8 * WSZ, 512, 256);

    // edge feature MLP (tensor cores)
    conv_hilo<<<32768, 256>>>(edgef, eHi_, eLo_, (size_t)EE * DD / 4);
    tc_gemm<1, 1><<<dim3(4, 512), 256, TC_SMEM>>>(eHi_, eLo_, WHi_ + 7 * WSZ, WLo_ + 7 * WSZ,
                                                  be1, nullptr, f1Hi_, f1Lo_, 512);
    tc_gemm<0, 0><<<dim3(2, 512), 256, TC_SMEM>>>(f1Hi_, f1Lo_, WHi_ + 8 * WSZ, WLo_ + 8 * WSZ,
                                                  be2, ef_, nullptr, nullptr, 256);

    // projections (tensor cores, sequential reuse of x split buffers)
    conv_hilo<<<2048, 256>>>(key, xHi_, xLo_, (size_t)ROWS * DD / 4);
    tc_gemm<0, 0><<<dim3(4, 32), 256, TC_SMEM>>>(xHi_, xLo_, WHi_ + 0 * WSZ, WLo_ + 0 * WSZ,
                                                 bk, k_, nullptr, nullptr, 512);
    conv_hilo<<<2048, 256>>>(query, xHi_, xLo_, (size_t)ROWS * DD / 4);
    tc_gemm<0, 0><<<dim3(4, 32), 256, TC_SMEM>>>(xHi_, xLo_, WHi_ + 1 * WSZ, WLo_ + 1 * WSZ,
                                                 bq, q_, nullptr, nullptr, 512);
    conv_hilo<<<2048, 256>>>(value, xHi_, xLo_, (size_t)ROWS * DD / 4);
    tc_gemm<0, 0><<<dim3(4, 32), 256, TC_SMEM>>>(xHi_, xLo_, WHi_ + 2 * WSZ, WLo_ + 2 * WSZ,
                                                 bv, v_, nullptr, nullptr, 512);

    // attention -> ctx
    local_attn<<<ROWS, 256>>>(q_, k_, v_, ef_, pair_j, ctx_);
    global_attn<<<dim3(64, 8, 8), 256>>>(q_, k_, v_, mask, ctx_, top);

    // output projection (emit f32 + hi/lo for downstream GEMMs)
    conv_hilo<<<2048, 256>>>(ctx_, xHi_, xLo_, (size_t)ROWS * DD / 4);
    tc_gemm<0, 2><<<dim3(4, 32), 256, TC_SMEM>>>(xHi_, xLo_, WHi_ + 3 * WSZ, WLo_ + 3 * WSZ,
                                                 bo, out, oHi_, oLo_, 512);

    // nf@Wu1 factored: P = out@Wu1_top + bu1 ; Q = out@Wu1_bot
    tc_gemm<0, 0><<<dim3(4, 32), 256, TC_SMEM>>>(oHi_, oLo_, WHi_ + 4 * WSZ, WLo_ + 4 * WSZ,
                                                 bu1, P_, nullptr, nullptr, 512);
    tc_gemm<0, 0><<<dim3(4, 32), 256, TC_SMEM>>>(oHi_, oLo_, WHi_ + 5 * WSZ, WLo_ + 5 * WSZ,
                                                 nullptr, Q_, nullptr, nullptr, 512);

    // eu = softplus(P_i + Q_j) - log2 -> bf16 hi/lo
    eu_kernel<<<EE, 128>>>(P_, Q_, pair_b, pair_i, pair_j, euHi_, euLo_);

    // edge_updated = eu @ Wu2 + bu2 (tensor cores)
    tc_gemm<0, 0><<<dim3(4, 512), 256, TC_SMEM>>>(euHi_, euLo_, WHi_ + 6 * WSZ, WLo_ + 6 * WSZ,
                                                  bu2, eupd, nullptr, nullptr, 512);
}

// round 5
// speedup vs baseline: 2.3112x; 1.2297x over previous
#include <cuda_runtime.h>
#include <cuda_bf16.h>
#include <cuda_fp16.h>
#include <math.h>
#include <stdint.h>

// Problem constants
#define BB 8
#define NN 512
#define DD 512
#define DEG_ 16
#define EE 65536   // B*N*DEG
#define ROWS 4096  // B*N
#define GK 512     // K dim of all big GEMMs
#define SCALE 0.17677669529663687f  // 1/sqrt(32)
#define LOG2F_ 0.6931471805599453f

// ---------------- scratch (device globals; no allocs allowed) ----------------
__device__ float g_q[ROWS * DD];
__device__ float g_k[ROWS * DD];
__device__ float g_v[ROWS * DD];
__device__ float g_ctx[ROWS * DD];
__device__ float g_PQ[ROWS * 1024];
__device__ float g_ef[(size_t)EE * 256];

__device__ __half g_eF[(size_t)EE * DD];
__device__ __half g_f1[(size_t)EE * DD];
__device__ __half g_eu[(size_t)EE * DD];
__device__ __half g_xK[ROWS * DD];
__device__ __half g_xQ[ROWS * DD];
__device__ __half g_xV[ROWS * DD];
__device__ __half g_xC[ROWS * DD];
__device__ __half g_o[ROWS * DD];

// weights (transposed [N,K], fp16 hi/lo): 0 Wk,1 Wq,2 Wv,3 Wo,4 Wu1a,5 Wu1b,6 Wu2,7 We1,8 We2(256x512)
__device__ __half g_WHi[9 * 262144];
__device__ __half g_WLo[9 * 262144];
__device__ float g_biasPQ[1024];

__device__ __forceinline__ float softplusf(float x) {
    return fmaxf(x, 0.f) + log1pf(expf(-fabsf(x)));
}

__device__ __forceinline__ uint32_t smem_to_u32(const void* smem_ptr) {
    uint32_t addr;
    asm("{ .reg .u64 tmp; cvta.to.shared.u64 tmp, %1; cvt.u32.u64 %0, tmp; }"
        : "=r"(addr) : "l"(smem_ptr));
    return addr;
}

// ---------------- PTX: cp.async / ldmatrix / mma (base-arch legal) ----------------
__device__ __forceinline__ void cpasync16(uint32_t saddr, const void* g) {
    asm volatile("cp.async.cg.shared.global [%0], [%1], 16;" :: "r"(saddr), "l"(g));
}
#define CP_COMMIT() asm volatile("cp.async.commit_group;")
#define CP_WAIT(n)  asm volatile("cp.async.wait_group %0;" :: "n"(n))

__device__ __forceinline__ void ldmx4(uint32_t r[4], uint32_t addr) {
    asm volatile("ldmatrix.sync.aligned.m8n8.x4.shared.b16 {%0,%1,%2,%3}, [%4];"
                 : "=r"(r[0]), "=r"(r[1]), "=r"(r[2]), "=r"(r[3]) : "r"(addr));
}

__device__ __forceinline__ void mma16816(float c[4], const uint32_t a[4],
                                         uint32_t b0, uint32_t b1) {
    asm volatile("mma.sync.aligned.m16n8k16.row.col.f32.f16.f16.f32 "
                 "{%0,%1,%2,%3}, {%4,%5,%6,%7}, {%8,%9}, {%0,%1,%2,%3};"
                 : "+f"(c[0]), "+f"(c[1]), "+f"(c[2]), "+f"(c[3])
                 : "r"(a[0]), "r"(a[1]), "r"(a[2]), "r"(a[3]), "r"(b0), "r"(b1));
}

__device__ __forceinline__ uint32_t packh2(float x, float y) {
    __half2 h = __floats2half2_rn(x, y);
    return *(uint32_t*)&h;
}

// ======================= tensor-core GEMM (mma.sync fp16, 2-term weight split) ===============
// C[M x N] = A[M x 512] @ (Whi + Wlo)^T.  A fp16 [M,512], W fp16 [N,512] K-major hi/lo.
// CTA 128x128, 8 warps of 32x64, BK=32, cp.async double buffer. Rows padded to 80B.
#define ROWB 80
#define TILE_B (128 * ROWB)      // 10240
#define A_OFF 0
#define BH_OFF (1 * TILE_B)
#define BL_OFF (2 * TILE_B)
#define STAGE_B (3 * TILE_B)     // 30720
#define TC_SMEM (2 * STAGE_B)    // 61440

__device__ __forceinline__ void load_stage(
    uint32_t sbase,
    const __half* __restrict__ A, const __half* __restrict__ Bhi, const __half* __restrict__ Blo,
    int bm, int bn, int kc, int t)
{
#pragma unroll
    for (int i = 0; i < 2; i++) {
        const int id = t + i * 256;           // 0..511
        const int row = id >> 2, ch = id & 3;
        const uint32_t soff = row * ROWB + ch * 16;
        const size_t gA = (size_t)(bm + row) * GK + kc * 32 + ch * 8;
        const size_t gB = (size_t)(bn + row) * GK + kc * 32 + ch * 8;
        cpasync16(sbase + A_OFF + soff, A + gA);
        cpasync16(sbase + BH_OFF + soff, Bhi + gB);
        cpasync16(sbase + BL_OFF + soff, Blo + gB);
    }
}

// OUT: 0 = f32 only, 1 = fp16 only, 2 = f32 + fp16
template <int SOFTPLUS, int OUT>
__global__ __launch_bounds__(256, 2) void tc_gemm(
    const __half* __restrict__ A,
    const __half* __restrict__ Bhi, const __half* __restrict__ Blo,
    const float* __restrict__ bias,
    float* __restrict__ Cf, __half* __restrict__ Ch,
    int N)
{
    extern __shared__ char smem[];
    const uint32_t sb = smem_to_u32(smem);
    const int t = threadIdx.x, lane = t & 31, w = t >> 5;
    const int wm = w & 3, wn = w >> 2;
    const int bm = blockIdx.y * 128, bn = blockIdx.x * 128;

    float acc[2][8][4] = {};

    const uint32_t aRow = (uint32_t)(wm * 32 + (lane & 15)) * ROWB + ((lane >> 4) << 4);
    const int n_off = (lane & 7) + ((lane >> 4) << 3);
    const int k_half = (lane >> 3) & 1;
    const uint32_t bRow = (uint32_t)(wn * 64 + n_off) * ROWB + (k_half << 4);

    load_stage(sb, A, Bhi, Blo, bm, bn, 0, t);
    CP_COMMIT();

    for (int kc = 0; kc < GK / 32; kc++) {
        const uint32_t cur = sb + (kc & 1) * STAGE_B;
        if (kc < GK / 32 - 1) {
            load_stage(sb + ((kc + 1) & 1) * STAGE_B, A, Bhi, Blo, bm, bn, kc + 1, t);
            CP_COMMIT();
            CP_WAIT(1);
        } else {
            CP_WAIT(0);
        }
        __syncthreads();

#pragma unroll
        for (int ks = 0; ks < 2; ks++) {
            const uint32_t kb = ks * 32;
            uint32_t a[2][4], bh[4][4], bl[4][4];
            ldmx4(a[0], cur + A_OFF + aRow + kb);
            ldmx4(a[1], cur + A_OFF + aRow + 16 * ROWB + kb);
#pragma unroll
            for (int jj = 0; jj < 4; jj++) {
                ldmx4(bh[jj], cur + BH_OFF + bRow + jj * 16 * ROWB + kb);
                ldmx4(bl[jj], cur + BL_OFF + bRow + jj * 16 * ROWB + kb);
            }
#pragma unroll
            for (int g = 0; g < 2; g++) {
#pragma unroll
                for (int j = 0; j < 8; j++) {
                    const int jj = j >> 1, hf = (j & 1) * 2;
                    mma16816(acc[g][j], a[g], bh[jj][hf], bh[jj][hf + 1]);
                    mma16816(acc[g][j], a[g], bl[jj][hf], bl[jj][hf + 1]);
                }
            }
        }
        __syncthreads();
    }

    // epilogue
#pragma unroll
    for (int g = 0; g < 2; g++) {
#pragma unroll
        for (int j = 0; j < 8; j++) {
            const int row = bm + wm * 32 + g * 16 + (lane >> 2);
            const int col = bn + wn * 64 + j * 8 + (lane & 3) * 2;
            float b0 = bias ? bias[col] : 0.f;
            float b1 = bias ? bias[col + 1] : 0.f;
            float v0 = acc[g][j][0] + b0, v1 = acc[g][j][1] + b1;
            float v2 = acc[g][j][2] + b0, v3 = acc[g][j][3] + b1;
            if (SOFTPLUS) {
                v0 = softplusf(v0) - LOG2F_; v1 = softplusf(v1) - LOG2F_;
                v2 = softplusf(v2) - LOG2F_; v3 = softplusf(v3) - LOG2F_;
            }
            if (OUT == 0 || OUT == 2) {
                *(float2*)(Cf + (size_t)row * N + col) = make_float2(v0, v1);
                *(float2*)(Cf + (size_t)(row + 8) * N + col) = make_float2(v2, v3);
            }
            if (OUT == 1 || OUT == 2) {
                *(uint32_t*)(Ch + (size_t)row * N + col) = packh2(v0, v1);
                *(uint32_t*)(Ch + (size_t)(row + 8) * N + col) = packh2(v2, v3);
            }
        }
    }
}

// ---------------- fp32 -> fp16 (vectorized) ----------------
__global__ __launch_bounds__(256) void conv_f16(
    const float* __restrict__ x, __half* __restrict__ y, size_t n4)
{
    size_t i = (size_t)blockIdx.x * 256 + threadIdx.x;
    if (i >= n4) return;
    float4 v = ((const float4*)x)[i];
    uint2 u;
    u.x = packh2(v.x, v.y);
    u.y = packh2(v.z, v.w);
    *(uint2*)(y + i * 4) = u;
}

// ---------------- all weights: transpose + fp16 hi/lo split, one launch ----------------
__global__ __launch_bounds__(256) void wsplit_all(
    const float* __restrict__ Wk, const float* __restrict__ Wq, const float* __restrict__ Wv,
    const float* __restrict__ Wo, const float* __restrict__ Wu1, const float* __restrict__ Wu2,
    const float* __restrict__ We1, const float* __restrict__ We2,
    const float* __restrict__ bu1,
    __half* __restrict__ WHi, __half* __restrict__ WLo, float* __restrict__ biasPQ)
{
    const int bid = blockIdx.x, t = threadIdx.x;
    if (bid < 8192) {
        const int seg = bid >> 10;
        const int idx = ((bid & 1023) << 8) | t;  // 0..262143
        const float* src;
        switch (seg) {
            case 0: src = Wk; break;
            case 1: src = Wq; break;
            case 2: src = Wv; break;
            case 3: src = Wo; break;
            case 4: src = Wu1; break;
            case 5: src = Wu1 + 262144; break;
            case 6: src = Wu2; break;
            default: src = We1; break;
        }
        const int k = idx >> 9, n = idx & 511;
        const float v = src[idx];
        const __half h = __float2half_rn(v);
        WHi[(size_t)seg * 262144 + (size_t)n * 512 + k] = h;
        WLo[(size_t)seg * 262144 + (size_t)n * 512 + k] = __float2half_rn(v - __half2float(h));
    } else if (bid < 8704) {
        const int idx = ((bid - 8192) << 8) | t;  // 0..131071  (We2: [512,256])
        const int k = idx >> 8, n = idx & 255;
        const float v = We2[idx];
        const __half h = __float2half_rn(v);
        WHi[(size_t)8 * 262144 + (size_t)n * 512 + k] = h;
        WLo[(size_t)8 * 262144 + (size_t)n * 512 + k] = __float2half_rn(v - __half2float(h));
    } else {
        const int i = ((bid - 8704) << 8) | t;  // 0..1023
        biasPQ[i] = (i < 512) ? bu1[i] : 0.f;
    }
}

// ---------------- local attention: one block per (b,i) ----------------
__global__ __launch_bounds__(256) void local_attn(
    const float* __restrict__ q, const float* __restrict__ k,
    const float* __restrict__ v, const float* __restrict__ ef,
    const int* __restrict__ pair_j, float* __restrict__ ctx)
{
    const int bi = blockIdx.x;
    const int b = bi >> 9;
    const int t = threadIdx.x;

    __shared__ float qs[256];
    __shared__ int js[16];
    __shared__ float sc[16][8];
    __shared__ float wgt[16][8];

    if (t < 16) js[t] = pair_j[bi * 16 + t];
    qs[t] = q[(size_t)bi * DD + 256 + t];
    __syncthreads();

    if (t < 128) {
        const int d = t >> 3, h = t & 7;
        const int j = js[d];
        const float* kr = k + ((size_t)(b * NN + j)) * DD + 256 + h * 32;
        const float* er = ef + ((size_t)(bi * 16 + d)) * 256 + h * 32;
        const float* qr = qs + h * 32;
        float s = 0.f;
#pragma unroll
        for (int c4 = 0; c4 < 8; c4++) {
            float4 kk = *(const float4*)(kr + c4 * 4);
            float4 eee = *(const float4*)(er + c4 * 4);
            s = fmaf(qr[c4 * 4 + 0], kk.x * eee.x, s);
            s = fmaf(qr[c4 * 4 + 1], kk.y * eee.y, s);
            s = fmaf(qr[c4 * 4 + 2], kk.z * eee.z, s);
            s = fmaf(qr[c4 * 4 + 3], kk.w * eee.w, s);
        }
        sc[d][h] = s * SCALE;
    }
    __syncthreads();

    if (t < 8) {
        const int h = t;
        float m = -1e30f;
#pragma unroll
        for (int d = 0; d < 16; d++) {
            float s = sc[d][h];
            if (s > -10000.f && s > m) m = s;
        }
        float sum = 0.f;
#pragma unroll
        for (int d = 0; d < 16; d++) {
            float s = sc[d][h];
            float e = (s > -10000.f) ? expf(s - m) : 0.f;
            wgt[d][h] = e;
            sum += e;
        }
        float inv = (sum > 0.f) ? 1.f / sum : 0.f;
#pragma unroll
        for (int d = 0; d < 16; d++) wgt[d][h] *= inv;
    }
    __syncthreads();

    const int h = t >> 5, c = t & 31;
    float o = 0.f;
#pragma unroll
    for (int d = 0; d < 16; d++) {
        float w = wgt[d][h];
        o = fmaf(w, v[((size_t)(b * NN + js[d])) * DD + 256 + h * 32 + c], o);
    }
    ctx[(size_t)bi * DD + h * 64 + 32 + c] = o;
}

// ---------------- global attention: block = (b, h, tile of 8 i) ----------------
__global__ __launch_bounds__(256) void global_attn(
    const float* __restrict__ q, const float* __restrict__ k,
    const float* __restrict__ v, const unsigned char* __restrict__ mask,
    float* __restrict__ ctx, float* __restrict__ top)
{
    const int b = blockIdx.z, h = blockIdx.y, it = blockIdx.x;
    const int t = threadIdx.x;

    __shared__ float Qs[8][32];
    __shared__ float Ks[64][32];
    __shared__ float S[8][512];

    {
        const int i = t >> 5, c = t & 31;
        Qs[i][c] = q[((size_t)(b * NN) + it * 8 + i) * DD + h * 32 + c] * SCALE;
    }

    const int lrow = t >> 2, lseg = (t & 3) * 8;

    for (int jt = 0; jt < 8; jt++) {
        const float* kr = k + ((size_t)(b * NN) + jt * 64 + lrow) * DD + h * 32 + lseg;
        float4 k0 = *(const float4*)kr;
        float4 k1 = *(const float4*)(kr + 4);
        __syncthreads();
        *(float4*)&Ks[lrow][lseg] = k0;
        *(float4*)&Ks[lrow][lseg + 4] = k1;
        __syncthreads();
#pragma unroll
        for (int r = 0; r < 2; r++) {
            const int idx = t + 256 * r;
            const int i = idx & 7, jl = idx >> 3;
            float s = 0.f;
#pragma unroll
            for (int c = 0; c < 32; c++) s = fmaf(Qs[i][c], Ks[jl][c], s);
            S[i][jt * 64 + jl] = s;
        }
    }
    __syncthreads();

    if (h == 0) {
#pragma unroll
        for (int r = 0; r < 16; r++) {
            const int idx = t + 256 * r;
            const int i = idx >> 9, j = idx & 511;
            top[((size_t)(b * NN) + it * 8 + i) * NN + j] = S[i][j];
        }
    }
#pragma unroll
    for (int r = 0; r < 16; r++) {
        const int idx = t + 256 * r;
        const int i = idx >> 9, j = idx & 511;
        if (mask[((size_t)(b * NN) + it * 8 + i) * NN + j]) S[i][j] = -1e18f;
    }
    __syncthreads();

    {
        const int i = t >> 5, lane = t & 31;
        float m = -1e30f;
        for (int j = lane; j < 512; j += 32) m = fmaxf(m, S[i][j]);
#pragma unroll
        for (int o = 16; o; o >>= 1) m = fmaxf(m, __shfl_xor_sync(0xffffffffu, m, o));
        float sum = 0.f;
        for (int j = lane; j < 512; j += 32) {
            float e = __expf(S[i][j] - m);
            S[i][j] = e;
            sum += e;
        }
#pragma unroll
        for (int o = 16; o; o >>= 1) sum += __shfl_xor_sync(0xffffffffu, sum, o);
        float inv = 1.f / sum;
        for (int j = lane; j < 512; j += 32) S[i][j] *= inv;
    }
    __syncthreads();

    const int i = t >> 5, c = t & 31;
    float acc = 0.f;
    for (int jt = 0; jt < 8; jt++) {
        const float* vr = v + ((size_t)(b * NN) + jt * 64 + lrow) * DD + h * 32 + lseg;
        float4 v0 = *(const float4*)vr;
        float4 v1 = *(const float4*)(vr + 4);
        __syncthreads();
        *(float4*)&Ks[lrow][lseg] = v0;
        *(float4*)&Ks[lrow][lseg + 4] = v1;
        __syncthreads();
#pragma unroll
        for (int jl = 0; jl < 64; jl++) acc = fmaf(S[i][jt * 64 + jl], Ks[jl][c], acc);
    }
    ctx[((size_t)(b * NN) + it * 8 + i) * DD + h * 64 + c] = acc;
}

// ---------------- eu = softplus(P[row_i] + Q[row_j]) - log2  -> fp16 ----------------
__global__ __launch_bounds__(128) void eu_kernel(
    const float* __restrict__ PQ,
    const int* __restrict__ pair_b, const int* __restrict__ pair_i,
    const int* __restrict__ pair_j,
    __half* __restrict__ eu)
{
    const int e = blockIdx.x;
    const int b = pair_b[e], i = pair_i[e], j = pair_j[e];
    const float4* pr = (const float4*)(PQ + ((size_t)(b * NN + i)) * 1024);
    const float4* qr = (const float4*)(PQ + ((size_t)(b * NN + j)) * 1024 + 512);
    const int t = threadIdx.x;
    float4 a = pr[t], c = qr[t];
    float r0 = softplusf(a.x + c.x) - LOG2F_;
    float r1 = softplusf(a.y + c.y) - LOG2F_;
    float r2 = softplusf(a.z + c.z) - LOG2F_;
    float r3 = softplusf(a.w + c.w) - LOG2F_;
    uint2 u;
    u.x = packh2(r0, r1);
    u.y = packh2(r2, r3);
    *(uint2*)(eu + (size_t)e * DD + t * 4) = u;
}

// ---------------- launch ----------------
extern "C" void kernel_launch(void* const* d_in, const int* in_sizes, int n_in,
                              void* d_out, int out_size)
{
    const float* key    = (const float*)d_in[0];
    const float* value  = (const float*)d_in[1];
    const float* query  = (const float*)d_in[2];
    const unsigned char* mask = (const unsigned char*)d_in[3];
    const float* edgef  = (const float*)d_in[4];
    const int* pair_b   = (const int*)d_in[5];
    const int* pair_i   = (const int*)d_in[6];
    const int* pair_j   = (const int*)d_in[7];
    const float* Wq = (const float*)d_in[8],  *bq = (const float*)d_in[9];
    const float* Wk = (const float*)d_in[10], *bk = (const float*)d_in[11];
    const float* Wv = (const float*)d_in[12], *bv = (const float*)d_in[13];
    const float* Wo = (const float*)d_in[14], *bo = (const float*)d_in[15];
    const float* We1 = (const float*)d_in[16], *be1 = (const float*)d_in[17];
    const float* We2 = (const float*)d_in[18], *be2 = (const float*)d_in[19];
    const float* Wu1 = (const float*)d_in[20], *bu1 = (const float*)d_in[21];
    const float* Wu2 = (const float*)d_in[22], *bu2 = (const float*)d_in[23];

    float* out  = (float*)d_out;
    float* top  = out + 2097152;
    float* eupd = out + 4194304;

    float *q_, *k_, *v_, *ctx_, *PQ_, *ef_, *biasPQ_;
    __half *eF_, *f1_, *eu_, *xK_, *xQ_, *xV_, *xC_, *o_, *WHi_, *WLo_;
    cudaGetSymbolAddress((void**)&q_, g_q);
    cudaGetSymbolAddress((void**)&k_, g_k);
    cudaGetSymbolAddress((void**)&v_, g_v);
    cudaGetSymbolAddress((void**)&ctx_, g_ctx);
    cudaGetSymbolAddress((void**)&PQ_, g_PQ);
    cudaGetSymbolAddress((void**)&ef_, g_ef);
    cudaGetSymbolAddress((void**)&eF_, g_eF);
    cudaGetSymbolAddress((void**)&f1_, g_f1);
    cudaGetSymbolAddress((void**)&eu_, g_eu);
    cudaGetSymbolAddress((void**)&xK_, g_xK);
    cudaGetSymbolAddress((void**)&xQ_, g_xQ);
    cudaGetSymbolAddress((void**)&xV_, g_xV);
    cudaGetSymbolAddress((void**)&xC_, g_xC);
    cudaGetSymbolAddress((void**)&o_, g_o);
    cudaGetSymbolAddress((void**)&WHi_, g_WHi);
    cudaGetSymbolAddress((void**)&WLo_, g_WLo);
    cudaGetSymbolAddress((void**)&biasPQ_, g_biasPQ);

    cudaFuncSetAttribute((const void*)tc_gemm<0, 0>,
                         cudaFuncAttributeMaxDynamicSharedMemorySize, TC_SMEM);
    cudaFuncSetAttribute((const void*)tc_gemm<1, 1>,
                         cudaFuncAttributeMaxDynamicSharedMemorySize, TC_SMEM);
    cudaFuncSetAttribute((const void*)tc_gemm<0, 2>,
                         cudaFuncAttributeMaxDynamicSharedMemorySize, TC_SMEM);

    const int WSZ = 262144;

    // all weight prep in one launch
    wsplit_all<<<8708, 256>>>(Wk, Wq, Wv, Wo, Wu1, Wu2, We1, We2, bu1,
                              WHi_, WLo_, biasPQ_);

    // input conversions
    conv_f16<<<32768, 256>>>(edgef, eF_, (size_t)EE * DD / 4);
    conv_f16<<<2048, 256>>>(key,   xK_, (size_t)ROWS * DD / 4);
    conv_f16<<<2048, 256>>>(query, xQ_, (size_t)ROWS * DD / 4);
    conv_f16<<<2048, 256>>>(value, xV_, (size_t)ROWS * DD / 4);

    // edge feature MLP (tensor cores)
    tc_gemm<1, 1><<<dim3(4, 512), 256, TC_SMEM>>>(eF_, WHi_ + 7 * WSZ, WLo_ + 7 * WSZ,
                                                  be1, nullptr, f1_, 512);
    tc_gemm<0, 0><<<dim3(2, 512), 256, TC_SMEM>>>(f1_, WHi_ + 8 * WSZ, WLo_ + 8 * WSZ,
                                                  be2, ef_, nullptr, 256);

    // projections
    tc_gemm<0, 0><<<dim3(4, 32), 256, TC_SMEM>>>(xK_, WHi_ + 0 * WSZ, WLo_ + 0 * WSZ,
                                                 bk, k_, nullptr, 512);
    tc_gemm<0, 0><<<dim3(4, 32), 256, TC_SMEM>>>(xQ_, WHi_ + 1 * WSZ, WLo_ + 1 * WSZ,
                                                 bq, q_, nullptr, 512);
    tc_gemm<0, 0><<<dim3(4, 32), 256, TC_SMEM>>>(xV_, WHi_ + 2 * WSZ, WLo_ + 2 * WSZ,
                                                 bv, v_, nullptr, 512);

    // attention -> ctx
    local_attn<<<ROWS, 256>>>(q_, k_, v_, ef_, pair_j, ctx_);
    global_attn<<<dim3(64, 8, 8), 256>>>(q_, k_, v_, mask, ctx_, top);

    // output projection (emit f32 + fp16 for downstream)
    conv_f16<<<2048, 256>>>(ctx_, xC_, (size_t)ROWS * DD / 4);
    tc_gemm<0, 2><<<dim3(4, 32), 256, TC_SMEM>>>(xC_, WHi_ + 3 * WSZ, WLo_ + 3 * WSZ,
                                                 bo, out, o_, 512);

    // P,Q in one GEMM over stacked Wu1 halves (N=1024)
    tc_gemm<0, 0><<<dim3(8, 32), 256, TC_SMEM>>>(o_, WHi_ + 4 * WSZ, WLo_ + 4 * WSZ,
                                                 biasPQ_, PQ_, nullptr, 1024);

    // eu = softplus(P_i + Q_j) - log2 -> fp16
    eu_kernel<<<EE, 128>>>(PQ_, pair_b, pair_i, pair_j, eu_);

    // edge_updated = eu @ Wu2 + bu2
    tc_gemm<0, 0><<<dim3(4, 512), 256, TC_SMEM>>>(eu_, WHi_ + 6 * WSZ, WLo_ + 6 * WSZ,
                                                  bu2, eupd, nullptr, 512);
}

// round 6
// speedup vs baseline: 3.0113x; 1.3030x over previous
#include <cuda_runtime.h>
#include <cuda_bf16.h>
#include <cuda_fp16.h>
#include <math.h>
#include <stdint.h>

// Problem constants
#define BB 8
#define NN 512
#define DD 512
#define DEG_ 16
#define EE 65536   // B*N*DEG
#define ROWS 4096  // B*N
#define GK 512     // K dim of all big GEMMs
#define SCALE 0.17677669529663687f  // 1/sqrt(32)
#define LOG2F_ 0.6931471805599453f

// ---------------- scratch (device globals; no allocs allowed) ----------------
__device__ float g_q[ROWS * DD];
__device__ float g_k[ROWS * DD];
__device__ float g_v[ROWS * DD];
__device__ float g_PQ[ROWS * 1024];
__device__ float g_ef[(size_t)EE * 256];

__device__ __half g_eF[(size_t)EE * DD];
__device__ __half g_f1[(size_t)EE * DD];
__device__ __half g_eu[(size_t)EE * DD];
__device__ __half g_xK[ROWS * DD];
__device__ __half g_xQ[ROWS * DD];
__device__ __half g_xV[ROWS * DD];
__device__ __half g_xC[ROWS * DD];   // ctx in fp16 (written by attention directly)
__device__ __half g_o[ROWS * DD];

// weights (transposed [N,K], fp16): 0 Wk,1 Wq,2 Wv,3 Wo,4 Wu1(N=1024),6 Wu2,7 We1,8 We2(256x512)
__device__ __half g_WHi[9 * 262144];
__device__ float g_biasPQ[1024];

__device__ __forceinline__ float softplusf(float x) {
    return fmaxf(x, 0.f) + log1pf(expf(-fabsf(x)));
}

__device__ __forceinline__ uint32_t smem_to_u32(const void* smem_ptr) {
    uint32_t addr;
    asm("{ .reg .u64 tmp; cvta.to.shared.u64 tmp, %1; cvt.u32.u64 %0, tmp; }"
        : "=r"(addr) : "l"(smem_ptr));
    return addr;
}

// ---------------- PTX: cp.async / ldmatrix / mma (base-arch legal) ----------------
__device__ __forceinline__ void cpasync16(uint32_t saddr, const void* g) {
    asm volatile("cp.async.cg.shared.global [%0], [%1], 16;" :: "r"(saddr), "l"(g));
}
#define CP_COMMIT() asm volatile("cp.async.commit_group;")
#define CP_WAIT(n)  asm volatile("cp.async.wait_group %0;" :: "n"(n))

__device__ __forceinline__ void ldmx4(uint32_t r[4], uint32_t addr) {
    asm volatile("ldmatrix.sync.aligned.m8n8.x4.shared.b16 {%0,%1,%2,%3}, [%4];"
                 : "=r"(r[0]), "=r"(r[1]), "=r"(r[2]), "=r"(r[3]) : "r"(addr));
}

__device__ __forceinline__ void mma16816(float c[4], const uint32_t a[4],
                                         uint32_t b0, uint32_t b1) {
    asm volatile("mma.sync.aligned.m16n8k16.row.col.f32.f16.f16.f32 "
                 "{%0,%1,%2,%3}, {%4,%5,%6,%7}, {%8,%9}, {%0,%1,%2,%3};"
                 : "+f"(c[0]), "+f"(c[1]), "+f"(c[2]), "+f"(c[3])
                 : "r"(a[0]), "r"(a[1]), "r"(a[2]), "r"(a[3]), "r"(b0), "r"(b1));
}

__device__ __forceinline__ uint32_t packh2(float x, float y) {
    __half2 h = __floats2half2_rn(x, y);
    return *(uint32_t*)&h;
}

// ======================= tensor-core GEMM (mma.sync fp16, 1-term weights) ===============
// C[M x N] = A[M x 512] @ W^T.  A fp16 [M,512], W fp16 [N,512] K-major.
// CTA 128x128, 8 warps of 32x64, BK=32, cp.async 3-stage pipeline. Rows padded to 80B.
#define ROWB 80
#define TILE_B (128 * ROWB)      // 10240
#define A_OFF 0
#define B_OFF (1 * TILE_B)
#define STAGE_B (2 * TILE_B)     // 20480
#define NSTAGE 3
#define TC_SMEM (NSTAGE * STAGE_B)  // 61440

__device__ __forceinline__ void load_stage(
    uint32_t sbase,
    const __half* __restrict__ A, const __half* __restrict__ B,
    int bm, int bn, int kc, int t)
{
#pragma unroll
    for (int i = 0; i < 2; i++) {
        const int id = t + i * 256;           // 0..511
        const int row = id >> 2, ch = id & 3;
        const uint32_t soff = row * ROWB + ch * 16;
        const size_t gA = (size_t)(bm + row) * GK + kc * 32 + ch * 8;
        const size_t gB = (size_t)(bn + row) * GK + kc * 32 + ch * 8;
        cpasync16(sbase + A_OFF + soff, A + gA);
        cpasync16(sbase + B_OFF + soff, B + gB);
    }
}

// OUT: 0 = f32 only, 1 = fp16 only, 2 = f32 + fp16
template <int SOFTPLUS, int OUT>
__global__ __launch_bounds__(256, 2) void tc_gemm(
    const __half* __restrict__ A, const __half* __restrict__ B,
    const float* __restrict__ bias,
    float* __restrict__ Cf, __half* __restrict__ Ch,
    int N)
{
    extern __shared__ char smem[];
    const uint32_t sb = smem_to_u32(smem);
    const int t = threadIdx.x, lane = t & 31, w = t >> 5;
    const int wm = w & 3, wn = w >> 2;
    const int bm = blockIdx.y * 128, bn = blockIdx.x * 128;
    const int KT = GK / 32;   // 16

    float acc[2][8][4] = {};

    const uint32_t aRow = (uint32_t)(wm * 32 + (lane & 15)) * ROWB + ((lane >> 4) << 4);
    const int n_off = (lane & 7) + ((lane >> 4) << 3);
    const int k_half = (lane >> 3) & 1;
    const uint32_t bRow = (uint32_t)(wn * 64 + n_off) * ROWB + (k_half << 4);

    load_stage(sb, A, B, bm, bn, 0, t);
    CP_COMMIT();
    load_stage(sb + STAGE_B, A, B, bm, bn, 1, t);
    CP_COMMIT();

    for (int kc = 0; kc < KT; kc++) {
        const uint32_t cur = sb + (kc % NSTAGE) * STAGE_B;
        if (kc + 2 < KT) {
            load_stage(sb + ((kc + 2) % NSTAGE) * STAGE_B, A, B, bm, bn, kc + 2, t);
            CP_COMMIT();
            CP_WAIT(2);
        } else if (kc + 1 < KT) {
            CP_WAIT(1);
        } else {
            CP_WAIT(0);
        }
        __syncthreads();

#pragma unroll
        for (int ks = 0; ks < 2; ks++) {
            const uint32_t kb = ks * 32;
            uint32_t a[2][4], bh[4][4];
            ldmx4(a[0], cur + A_OFF + aRow + kb);
            ldmx4(a[1], cur + A_OFF + aRow + 16 * ROWB + kb);
#pragma unroll
            for (int jj = 0; jj < 4; jj++)
                ldmx4(bh[jj], cur + B_OFF + bRow + jj * 16 * ROWB + kb);
#pragma unroll
            for (int g = 0; g < 2; g++) {
#pragma unroll
                for (int j = 0; j < 8; j++) {
                    const int jj = j >> 1, hf = (j & 1) * 2;
                    mma16816(acc[g][j], a[g], bh[jj][hf], bh[jj][hf + 1]);
                }
            }
        }
        __syncthreads();
    }

    // epilogue
#pragma unroll
    for (int g = 0; g < 2; g++) {
#pragma unroll
        for (int j = 0; j < 8; j++) {
            const int row = bm + wm * 32 + g * 16 + (lane >> 2);
            const int col = bn + wn * 64 + j * 8 + (lane & 3) * 2;
            float b0 = bias ? bias[col] : 0.f;
            float b1 = bias ? bias[col + 1] : 0.f;
            float v0 = acc[g][j][0] + b0, v1 = acc[g][j][1] + b1;
            float v2 = acc[g][j][2] + b0, v3 = acc[g][j][3] + b1;
            if (SOFTPLUS) {
                v0 = softplusf(v0) - LOG2F_; v1 = softplusf(v1) - LOG2F_;
                v2 = softplusf(v2) - LOG2F_; v3 = softplusf(v3) - LOG2F_;
            }
            if (OUT == 0 || OUT == 2) {
                *(float2*)(Cf + (size_t)row * N + col) = make_float2(v0, v1);
                *(float2*)(Cf + (size_t)(row + 8) * N + col) = make_float2(v2, v3);
            }
            if (OUT == 1 || OUT == 2) {
                *(uint32_t*)(Ch + (size_t)row * N + col) = packh2(v0, v1);
                *(uint32_t*)(Ch + (size_t)(row + 8) * N + col) = packh2(v2, v3);
            }
        }
    }
}

// ---------------- fp32 -> fp16 (vectorized) ----------------
__global__ __launch_bounds__(256) void conv_f16(
    const float* __restrict__ x, __half* __restrict__ y, size_t n4)
{
    size_t i = (size_t)blockIdx.x * 256 + threadIdx.x;
    if (i >= n4) return;
    float4 v = ((const float4*)x)[i];
    uint2 u;
    u.x = packh2(v.x, v.y);
    u.y = packh2(v.z, v.w);
    *(uint2*)(y + i * 4) = u;
}

// key/query/value conversions in one launch (each 4096x512 -> 524288 f4 groups, 2048 blocks each)
__global__ __launch_bounds__(256) void conv3_f16(
    const float* __restrict__ k, const float* __restrict__ q, const float* __restrict__ v,
    __half* __restrict__ xk, __half* __restrict__ xq, __half* __restrict__ xv)
{
    const int seg = blockIdx.x >> 11;
    const size_t i = (size_t)(blockIdx.x & 2047) * 256 + threadIdx.x;
    const float* x = (seg == 0) ? k : (seg == 1) ? q : v;
    __half* y = (seg == 0) ? xk : (seg == 1) ? xq : xv;
    float4 val = ((const float4*)x)[i];
    uint2 u;
    u.x = packh2(val.x, val.y);
    u.y = packh2(val.z, val.w);
    *(uint2*)(y + i * 4) = u;
}

// ---------------- all weights: transpose + fp16, one launch ----------------
__global__ __launch_bounds__(256) void wsplit_all(
    const float* __restrict__ Wk, const float* __restrict__ Wq, const float* __restrict__ Wv,
    const float* __restrict__ Wo, const float* __restrict__ Wu1, const float* __restrict__ Wu2,
    const float* __restrict__ We1, const float* __restrict__ We2,
    const float* __restrict__ bu1,
    __half* __restrict__ WHi, float* __restrict__ biasPQ)
{
    const int bid = blockIdx.x, t = threadIdx.x;
    if (bid < 8192) {
        const int seg = bid >> 10;
        const int idx = ((bid & 1023) << 8) | t;  // 0..262143
        const float* src;
        switch (seg) {
            case 0: src = Wk; break;
            case 1: src = Wq; break;
            case 2: src = Wv; break;
            case 3: src = Wo; break;
            case 4: src = Wu1; break;
            case 5: src = Wu1 + 262144; break;
            case 6: src = Wu2; break;
            default: src = We1; break;
        }
        const int k = idx >> 9, n = idx & 511;
        WHi[(size_t)seg * 262144 + (size_t)n * 512 + k] = __float2half_rn(src[idx]);
    } else if (bid < 8704) {
        const int idx = ((bid - 8192) << 8) | t;  // 0..131071  (We2: [512,256])
        const int k = idx >> 8, n = idx & 255;
        WHi[(size_t)8 * 262144 + (size_t)n * 512 + k] = __float2half_rn(We2[idx]);
    } else {
        const int i = ((bid - 8704) << 8) | t;  // 0..1023
        biasPQ[i] = (i < 512) ? bu1[i] : 0.f;
    }
}

// ---------------- local attention: one block per (b,i), ctx written fp16 ----------------
__global__ __launch_bounds__(256) void local_attn(
    const float* __restrict__ q, const float* __restrict__ k,
    const float* __restrict__ v, const float* __restrict__ ef,
    const int* __restrict__ pair_j, __half* __restrict__ ctx)
{
    const int bi = blockIdx.x;
    const int b = bi >> 9;
    const int t = threadIdx.x;

    __shared__ float qs[256];
    __shared__ int js[16];
    __shared__ float sc[16][8];
    __shared__ float wgt[16][8];

    if (t < 16) js[t] = pair_j[bi * 16 + t];
    qs[t] = q[(size_t)bi * DD + 256 + t];
    __syncthreads();

    if (t < 128) {
        const int d = t >> 3, h = t & 7;
        const int j = js[d];
        const float* kr = k + ((size_t)(b * NN + j)) * DD + 256 + h * 32;
        const float* er = ef + ((size_t)(bi * 16 + d)) * 256 + h * 32;
        const float* qr = qs + h * 32;
        float s = 0.f;
#pragma unroll
        for (int c4 = 0; c4 < 8; c4++) {
            float4 kk = *(const float4*)(kr + c4 * 4);
            float4 eee = *(const float4*)(er + c4 * 4);
            s = fmaf(qr[c4 * 4 + 0], kk.x * eee.x, s);
            s = fmaf(qr[c4 * 4 + 1], kk.y * eee.y, s);
            s = fmaf(qr[c4 * 4 + 2], kk.z * eee.z, s);
            s = fmaf(qr[c4 * 4 + 3], kk.w * eee.w, s);
        }
        sc[d][h] = s * SCALE;
    }
    __syncthreads();

    if (t < 8) {
        const int h = t;
        float m = -1e30f;
#pragma unroll
        for (int d = 0; d < 16; d++) {
            float s = sc[d][h];
            if (s > -10000.f && s > m) m = s;
        }
        float sum = 0.f;
#pragma unroll
        for (int d = 0; d < 16; d++) {
            float s = sc[d][h];
            float e = (s > -10000.f) ? expf(s - m) : 0.f;
            wgt[d][h] = e;
            sum += e;
        }
        float inv = (sum > 0.f) ? 1.f / sum : 0.f;
#pragma unroll
        for (int d = 0; d < 16; d++) wgt[d][h] *= inv;
    }
    __syncthreads();

    const int h = t >> 5, c = t & 31;
    float o = 0.f;
#pragma unroll
    for (int d = 0; d < 16; d++) {
        float w = wgt[d][h];
        o = fmaf(w, v[((size_t)(b * NN + js[d])) * DD + 256 + h * 32 + c], o);
    }
    ctx[(size_t)bi * DD + h * 64 + 32 + c] = __float2half_rn(o);
}

// ---------------- global attention: block = (b, h, tile of 8 i), ctx written fp16 ----------------
__global__ __launch_bounds__(256) void global_attn(
    const float* __restrict__ q, const float* __restrict__ k,
    const float* __restrict__ v, const unsigned char* __restrict__ mask,
    __half* __restrict__ ctx, float* __restrict__ top)
{
    const int b = blockIdx.z, h = blockIdx.y, it = blockIdx.x;
    const int t = threadIdx.x;

    __shared__ float Qs[8][32];
    __shared__ float Ks[64][32];
    __shared__ float S[8][512];

    {
        const int i = t >> 5, c = t & 31;
        Qs[i][c] = q[((size_t)(b * NN) + it * 8 + i) * DD + h * 32 + c] * SCALE;
    }

    const int lrow = t >> 2, lseg = (t & 3) * 8;

    for (int jt = 0; jt < 8; jt++) {
        const float* kr = k + ((size_t)(b * NN) + jt * 64 + lrow) * DD + h * 32 + lseg;
        float4 k0 = *(const float4*)kr;
        float4 k1 = *(const float4*)(kr + 4);
        __syncthreads();
        *(float4*)&Ks[lrow][lseg] = k0;
        *(float4*)&Ks[lrow][lseg + 4] = k1;
        __syncthreads();
#pragma unroll
        for (int r = 0; r < 2; r++) {
            const int idx = t + 256 * r;
            const int i = idx & 7, jl = idx >> 3;
            float s = 0.f;
#pragma unroll
            for (int c = 0; c < 32; c++) s = fmaf(Qs[i][c], Ks[jl][c], s);
            S[i][jt * 64 + jl] = s;
        }
    }
    __syncthreads();

    if (h == 0) {
#pragma unroll
        for (int r = 0; r < 16; r++) {
            const int idx = t + 256 * r;
            const int i = idx >> 9, j = idx & 511;
            top[((size_t)(b * NN) + it * 8 + i) * NN + j] = S[i][j];
        }
    }
#pragma unroll
    for (int r = 0; r < 16; r++) {
        const int idx = t + 256 * r;
        const int i = idx >> 9, j = idx & 511;
        if (mask[((size_t)(b * NN) + it * 8 + i) * NN + j]) S[i][j] = -1e18f;
    }
    __syncthreads();

    {
        const int i = t >> 5, lane = t & 31;
        float m = -1e30f;
        for (int j = lane; j < 512; j += 32) m = fmaxf(m, S[i][j]);
#pragma unroll
        for (int o = 16; o; o >>= 1) m = fmaxf(m, __shfl_xor_sync(0xffffffffu, m, o));
        float sum = 0.f;
        for (int j = lane; j < 512; j += 32) {
            float e = __expf(S[i][j] - m);
            S[i][j] = e;
            sum += e;
        }
#pragma unroll
        for (int o = 16; o; o >>= 1) sum += __shfl_xor_sync(0xffffffffu, sum, o);
        float inv = 1.f / sum;
        for (int j = lane; j < 512; j += 32) S[i][j] *= inv;
    }
    __syncthreads();

    const int i = t >> 5, c = t & 31;
    float acc = 0.f;
    for (int jt = 0; jt < 8; jt++) {
        const float* vr = v + ((size_t)(b * NN) + jt * 64 + lrow) * DD + h * 32 + lseg;
        float4 v0 = *(const float4*)vr;
        float4 v1 = *(const float4*)(vr + 4);
        __syncthreads();
        *(float4*)&Ks[lrow][lseg] = v0;
        *(float4*)&Ks[lrow][lseg + 4] = v1;
        __syncthreads();
#pragma unroll
        for (int jl = 0; jl < 64; jl++) acc = fmaf(S[i][jt * 64 + jl], Ks[jl][c], acc);
    }
    ctx[((size_t)(b * NN) + it * 8 + i) * DD + h * 64 + c] = __float2half_rn(acc);
}

// ---------------- eu: one block per (b,i); P row in regs, 16 edges ----------------
__global__ __launch_bounds__(128) void eu_kernel(
    const float* __restrict__ PQ,
    const int* __restrict__ pair_j,
    __half* __restrict__ eu)
{
    const int bi = blockIdx.x;          // b*N + i
    const int b = bi >> 9;
    const int t = threadIdx.x;          // 0..127 -> 4 floats each

    __shared__ int js[16];
    if (t < 16) js[t] = pair_j[bi * 16 + t];

    const float4 p = *(const float4*)(PQ + (size_t)bi * 1024 + t * 4);
    __syncthreads();

#pragma unroll 4
    for (int d = 0; d < 16; d++) {
        const int j = js[d];
        float4 c = *(const float4*)(PQ + ((size_t)(b * NN + j)) * 1024 + 512 + t * 4);
        float r0 = softplusf(p.x + c.x) - LOG2F_;
        float r1 = softplusf(p.y + c.y) - LOG2F_;
        float r2 = softplusf(p.z + c.z) - LOG2F_;
        float r3 = softplusf(p.w + c.w) - LOG2F_;
        uint2 u;
        u.x = packh2(r0, r1);
        u.y = packh2(r2, r3);
        *(uint2*)(eu + ((size_t)(bi * 16 + d)) * DD + t * 4) = u;
    }
}

// ---------------- launch ----------------
extern "C" void kernel_launch(void* const* d_in, const int* in_sizes, int n_in,
                              void* d_out, int out_size)
{
    const float* key    = (const float*)d_in[0];
    const float* value  = (const float*)d_in[1];
    const float* query  = (const float*)d_in[2];
    const unsigned char* mask = (const unsigned char*)d_in[3];
    const float* edgef  = (const float*)d_in[4];
    const int* pair_b   = (const int*)d_in[5];
    const int* pair_i   = (const int*)d_in[6];
    const int* pair_j   = (const int*)d_in[7];
    const float* Wq = (const float*)d_in[8],  *bq = (const float*)d_in[9];
    const float* Wk = (const float*)d_in[10], *bk = (const float*)d_in[11];
    const float* Wv = (const float*)d_in[12], *bv = (const float*)d_in[13];
    const float* Wo = (const float*)d_in[14], *bo = (const float*)d_in[15];
    const float* We1 = (const float*)d_in[16], *be1 = (const float*)d_in[17];
    const float* We2 = (const float*)d_in[18], *be2 = (const float*)d_in[19];
    const float* Wu1 = (const float*)d_in[20], *bu1 = (const float*)d_in[21];
    const float* Wu2 = (const float*)d_in[22], *bu2 = (const float*)d_in[23];

    float* out  = (float*)d_out;
    float* top  = out + 2097152;
    float* eupd = out + 4194304;

    float *q_, *k_, *v_, *PQ_, *ef_, *biasPQ_;
    __half *eF_, *f1_, *eu_, *xK_, *xQ_, *xV_, *xC_, *o_, *WHi_;
    cudaGetSymbolAddress((void**)&q_, g_q);
    cudaGetSymbolAddress((void**)&k_, g_k);
    cudaGetSymbolAddress((void**)&v_, g_v);
    cudaGetSymbolAddress((void**)&PQ_, g_PQ);
    cudaGetSymbolAddress((void**)&ef_, g_ef);
    cudaGetSymbolAddress((void**)&eF_, g_eF);
    cudaGetSymbolAddress((void**)&f1_, g_f1);
    cudaGetSymbolAddress((void**)&eu_, g_eu);
    cudaGetSymbolAddress((void**)&xK_, g_xK);
    cudaGetSymbolAddress((void**)&xQ_, g_xQ);
    cudaGetSymbolAddress((void**)&xV_, g_xV);
    cudaGetSymbolAddress((void**)&xC_, g_xC);
    cudaGetSymbolAddress((void**)&o_, g_o);
    cudaGetSymbolAddress((void**)&WHi_, g_WHi);
    cudaGetSymbolAddress((void**)&biasPQ_, g_biasPQ);

    cudaFuncSetAttribute((const void*)tc_gemm<0, 0>,
                         cudaFuncAttributeMaxDynamicSharedMemorySize, TC_SMEM);
    cudaFuncSetAttribute((const void*)tc_gemm<1, 1>,
                         cudaFuncAttributeMaxDynamicSharedMemorySize, TC_SMEM);
    cudaFuncSetAttribute((const void*)tc_gemm<0, 2>,
                         cudaFuncAttributeMaxDynamicSharedMemorySize, TC_SMEM);

    const int WSZ = 262144;

    // all weight prep in one launch
    wsplit_all<<<8708, 256>>>(Wk, Wq, Wv, Wo, Wu1, Wu2, We1, We2, bu1,
                              WHi_, biasPQ_);

    // input conversions
    conv_f16<<<32768, 256>>>(edgef, eF_, (size_t)EE * DD / 4);
    conv3_f16<<<6144, 256>>>(key, query, value, xK_, xQ_, xV_);

    // edge feature MLP (tensor cores)
    tc_gemm<1, 1><<<dim3(4, 512), 256, TC_SMEM>>>(eF_, WHi_ + 7 * WSZ,
                                                  be1, nullptr, f1_, 512);
    tc_gemm<0, 0><<<dim3(2, 512), 256, TC_SMEM>>>(f1_, WHi_ + 8 * WSZ,
                                                  be2, ef_, nullptr, 256);

    // projections
    tc_gemm<0, 0><<<dim3(4, 32), 256, TC_SMEM>>>(xK_, WHi_ + 0 * WSZ,
                                                 bk, k_, nullptr, 512);
    tc_gemm<0, 0><<<dim3(4, 32), 256, TC_SMEM>>>(xQ_, WHi_ + 1 * WSZ,
                                                 bq, q_, nullptr, 512);
    tc_gemm<0, 0><<<dim3(4, 32), 256, TC_SMEM>>>(xV_, WHi_ + 2 * WSZ,
                                                 bv, v_, nullptr, 512);

    // attention -> ctx (fp16 direct)
    local_attn<<<ROWS, 256>>>(q_, k_, v_, ef_, pair_j, xC_);
    global_attn<<<dim3(64, 8, 8), 256>>>(q_, k_, v_, mask, xC_, top);

    // output projection (emit f32 out + fp16 o for downstream)
    tc_gemm<0, 2><<<dim3(4, 32), 256, TC_SMEM>>>(xC_, WHi_ + 3 * WSZ,
                                                 bo, out, o_, 512);

    // P,Q in one GEMM over stacked Wu1 halves (N=1024)
    tc_gemm<0, 0><<<dim3(8, 32), 256, TC_SMEM>>>(o_, WHi_ + 4 * WSZ,
                                                 biasPQ_, PQ_, nullptr, 1024);

    // eu = softplus(P_i + Q_j) - log2 -> fp16
    eu_kernel<<<ROWS, 128>>>(PQ_, pair_j, eu_);

    // edge_updated = eu @ Wu2 + bu2
    tc_gemm<0, 0><<<dim3(4, 512), 256, TC_SMEM>>>(eu_, WHi_ + 6 * WSZ,
                                                  bu2, eupd, nullptr, 512);
}

// round 7
// speedup vs baseline: 5.1057x; 1.6955x over previous
#include <cuda_runtime.h>
#include <cuda_bf16.h>
#include <cuda_fp16.h>
#include <math.h>
#include <stdint.h>

// Problem constants
#define BB 8
#define NN 512
#define DD 512
#define DEG_ 16
#define EE 65536   // B*N*DEG
#define ROWS 4096  // B*N
#define GK 512     // K dim of all big GEMMs
#define SCALE 0.17677669529663687f  // 1/sqrt(32)
#define LOG2F_ 0.6931471805599453f

// ---------------- scratch (device globals; no allocs allowed) ----------------
__device__ float g_q[ROWS * DD];
__device__ float g_k[ROWS * DD];
__device__ float g_v[ROWS * DD];
__device__ float g_PQ[ROWS * 1024];
__device__ float g_ef[(size_t)EE * 256];

__device__ __half g_eF[(size_t)EE * DD];
__device__ __half g_f1[(size_t)EE * DD];
__device__ __half g_eu[(size_t)EE * DD];
__device__ __half g_xK[ROWS * DD];
__device__ __half g_xQ[ROWS * DD];
__device__ __half g_xV[ROWS * DD];
__device__ __half g_xC[ROWS * DD];   // ctx in fp16 (written by attention directly)
__device__ __half g_o[ROWS * DD];

// weights (transposed [N,K], fp16): 0 Wk,1 Wq,2 Wv,3 Wo,4 Wu1(N=1024),6 Wu2,7 We1,8 We2(256x512)
__device__ __half g_WHi[9 * 262144];
__device__ float g_biasPQ[1024];

__device__ __forceinline__ float softplusf(float x) {
    return fmaxf(x, 0.f) + log1pf(expf(-fabsf(x)));
}

__device__ __forceinline__ uint32_t smem_to_u32(const void* smem_ptr) {
    uint32_t addr;
    asm("{ .reg .u64 tmp; cvta.to.shared.u64 tmp, %1; cvt.u32.u64 %0, tmp; }"
        : "=r"(addr) : "l"(smem_ptr));
    return addr;
}

// ---------------- PTX: cp.async / ldmatrix / mma (base-arch legal) ----------------
__device__ __forceinline__ void cpasync16(uint32_t saddr, const void* g) {
    asm volatile("cp.async.cg.shared.global [%0], [%1], 16;" :: "r"(saddr), "l"(g));
}
#define CP_COMMIT() asm volatile("cp.async.commit_group;")
#define CP_WAIT(n)  asm volatile("cp.async.wait_group %0;" :: "n"(n))

__device__ __forceinline__ void ldmx4(uint32_t r[4], uint32_t addr) {
    asm volatile("ldmatrix.sync.aligned.m8n8.x4.shared.b16 {%0,%1,%2,%3}, [%4];"
                 : "=r"(r[0]), "=r"(r[1]), "=r"(r[2]), "=r"(r[3]) : "r"(addr));
}

__device__ __forceinline__ void mma16816(float c[4], const uint32_t a[4],
                                         uint32_t b0, uint32_t b1) {
    asm volatile("mma.sync.aligned.m16n8k16.row.col.f32.f16.f16.f32 "
                 "{%0,%1,%2,%3}, {%4,%5,%6,%7}, {%8,%9}, {%0,%1,%2,%3};"
                 : "+f"(c[0]), "+f"(c[1]), "+f"(c[2]), "+f"(c[3])
                 : "r"(a[0]), "r"(a[1]), "r"(a[2]), "r"(a[3]), "r"(b0), "r"(b1));
}

__device__ __forceinline__ uint32_t packh2(float x, float y) {
    __half2 h = __floats2half2_rn(x, y);
    return *(uint32_t*)&h;
}

// ======================= tensor-core GEMM (mma.sync fp16, 1-term weights) ===============
#define ROWB 80
#define TILE_B (128 * ROWB)      // 10240
#define A_OFF 0
#define B_OFF (1 * TILE_B)
#define STAGE_B (2 * TILE_B)     // 20480
#define NSTAGE 3
#define TC_SMEM (NSTAGE * STAGE_B)  // 61440

__device__ __forceinline__ void load_stage(
    uint32_t sbase,
    const __half* __restrict__ A, const __half* __restrict__ B,
    int bm, int bn, int kc, int t)
{
#pragma unroll
    for (int i = 0; i < 2; i++) {
        const int id = t + i * 256;           // 0..511
        const int row = id >> 2, ch = id & 3;
        const uint32_t soff = row * ROWB + ch * 16;
        const size_t gA = (size_t)(bm + row) * GK + kc * 32 + ch * 8;
        const size_t gB = (size_t)(bn + row) * GK + kc * 32 + ch * 8;
        cpasync16(sbase + A_OFF + soff, A + gA);
        cpasync16(sbase + B_OFF + soff, B + gB);
    }
}

// OUT: 0 = f32 only, 1 = fp16 only, 2 = f32 + fp16
template <int SOFTPLUS, int OUT>
__global__ __launch_bounds__(256, 2) void tc_gemm(
    const __half* __restrict__ A, const __half* __restrict__ B,
    const float* __restrict__ bias,
    float* __restrict__ Cf, __half* __restrict__ Ch,
    int N)
{
    extern __shared__ char smem[];
    const uint32_t sb = smem_to_u32(smem);
    const int t = threadIdx.x, lane = t & 31, w = t >> 5;
    const int wm = w & 3, wn = w >> 2;
    const int bm = blockIdx.y * 128, bn = blockIdx.x * 128;
    const int KT = GK / 32;   // 16

    float acc[2][8][4] = {};

    const uint32_t aRow = (uint32_t)(wm * 32 + (lane & 15)) * ROWB + ((lane >> 4) << 4);
    const int n_off = (lane & 7) + ((lane >> 4) << 3);
    const int k_half = (lane >> 3) & 1;
    const uint32_t bRow = (uint32_t)(wn * 64 + n_off) * ROWB + (k_half << 4);

    load_stage(sb, A, B, bm, bn, 0, t);
    CP_COMMIT();
    load_stage(sb + STAGE_B, A, B, bm, bn, 1, t);
    CP_COMMIT();

    for (int kc = 0; kc < KT; kc++) {
        const uint32_t cur = sb + (kc % NSTAGE) * STAGE_B;
        if (kc + 2 < KT) {
            load_stage(sb + ((kc + 2) % NSTAGE) * STAGE_B, A, B, bm, bn, kc + 2, t);
            CP_COMMIT();
            CP_WAIT(2);
        } else if (kc + 1 < KT) {
            CP_WAIT(1);
        } else {
            CP_WAIT(0);
        }
        __syncthreads();

#pragma unroll
        for (int ks = 0; ks < 2; ks++) {
            const uint32_t kb = ks * 32;
            uint32_t a[2][4], bh[4][4];
            ldmx4(a[0], cur + A_OFF + aRow + kb);
            ldmx4(a[1], cur + A_OFF + aRow + 16 * ROWB + kb);
#pragma unroll
            for (int jj = 0; jj < 4; jj++)
                ldmx4(bh[jj], cur + B_OFF + bRow + jj * 16 * ROWB + kb);
#pragma unroll
            for (int g = 0; g < 2; g++) {
#pragma unroll
                for (int j = 0; j < 8; j++) {
                    const int jj = j >> 1, hf = (j & 1) * 2;
                    mma16816(acc[g][j], a[g], bh[jj][hf], bh[jj][hf + 1]);
                }
            }
        }
        __syncthreads();
    }

    // epilogue
#pragma unroll
    for (int g = 0; g < 2; g++) {
#pragma unroll
        for (int j = 0; j < 8; j++) {
            const int row = bm + wm * 32 + g * 16 + (lane >> 2);
            const int col = bn + wn * 64 + j * 8 + (lane & 3) * 2;
            float b0 = bias ? bias[col] : 0.f;
            float b1 = bias ? bias[col + 1] : 0.f;
            float v0 = acc[g][j][0] + b0, v1 = acc[g][j][1] + b1;
            float v2 = acc[g][j][2] + b0, v3 = acc[g][j][3] + b1;
            if (SOFTPLUS) {
                v0 = softplusf(v0) - LOG2F_; v1 = softplusf(v1) - LOG2F_;
                v2 = softplusf(v2) - LOG2F_; v3 = softplusf(v3) - LOG2F_;
            }
            if (OUT == 0 || OUT == 2) {
                *(float2*)(Cf + (size_t)row * N + col) = make_float2(v0, v1);
                *(float2*)(Cf + (size_t)(row + 8) * N + col) = make_float2(v2, v3);
            }
            if (OUT == 1 || OUT == 2) {
                *(uint32_t*)(Ch + (size_t)row * N + col) = packh2(v0, v1);
                *(uint32_t*)(Ch + (size_t)(row + 8) * N + col) = packh2(v2, v3);
            }
        }
    }
}

// ---------------- fp32 -> fp16 (vectorized) ----------------
__global__ __launch_bounds__(256) void conv_f16(
    const float* __restrict__ x, __half* __restrict__ y, size_t n4)
{
    size_t i = (size_t)blockIdx.x * 256 + threadIdx.x;
    if (i >= n4) return;
    float4 v = ((const float4*)x)[i];
    uint2 u;
    u.x = packh2(v.x, v.y);
    u.y = packh2(v.z, v.w);
    *(uint2*)(y + i * 4) = u;
}

// key/query/value conversions in one launch
__global__ __launch_bounds__(256) void conv3_f16(
    const float* __restrict__ k, const float* __restrict__ q, const float* __restrict__ v,
    __half* __restrict__ xk, __half* __restrict__ xq, __half* __restrict__ xv)
{
    const int seg = blockIdx.x >> 11;
    const size_t i = (size_t)(blockIdx.x & 2047) * 256 + threadIdx.x;
    const float* x = (seg == 0) ? k : (seg == 1) ? q : v;
    __half* y = (seg == 0) ? xk : (seg == 1) ? xq : xv;
    float4 val = ((const float4*)x)[i];
    uint2 u;
    u.x = packh2(val.x, val.y);
    u.y = packh2(val.z, val.w);
    *(uint2*)(y + i * 4) = u;
}

// ---------------- all weights: transpose + fp16, one launch ----------------
__global__ __launch_bounds__(256) void wsplit_all(
    const float* __restrict__ Wk, const float* __restrict__ Wq, const float* __restrict__ Wv,
    const float* __restrict__ Wo, const float* __restrict__ Wu1, const float* __restrict__ Wu2,
    const float* __restrict__ We1, const float* __restrict__ We2,
    const float* __restrict__ bu1,
    __half* __restrict__ WHi, float* __restrict__ biasPQ)
{
    const int bid = blockIdx.x, t = threadIdx.x;
    if (bid < 8192) {
        const int seg = bid >> 10;
        const int idx = ((bid & 1023) << 8) | t;  // 0..262143
        const float* src;
        switch (seg) {
            case 0: src = Wk; break;
            case 1: src = Wq; break;
            case 2: src = Wv; break;
            case 3: src = Wo; break;
            case 4: src = Wu1; break;
            case 5: src = Wu1 + 262144; break;
            case 6: src = Wu2; break;
            default: src = We1; break;
        }
        const int k = idx >> 9, n = idx & 511;
        WHi[(size_t)seg * 262144 + (size_t)n * 512 + k] = __float2half_rn(src[idx]);
    } else if (bid < 8704) {
        const int idx = ((bid - 8192) << 8) | t;  // We2: [512,256]
        const int k = idx >> 8, n = idx & 255;
        WHi[(size_t)8 * 262144 + (size_t)n * 512 + k] = __float2half_rn(We2[idx]);
    } else {
        const int i = ((bid - 8704) << 8) | t;
        biasPQ[i] = (i < 512) ? bu1[i] : 0.f;
    }
}

// ---------------- local attention: one block per (b,i), ctx written fp16 ----------------
__global__ __launch_bounds__(256) void local_attn(
    const float* __restrict__ q, const float* __restrict__ k,
    const float* __restrict__ v, const float* __restrict__ ef,
    const int* __restrict__ pair_j, __half* __restrict__ ctx)
{
    const int bi = blockIdx.x;
    const int b = bi >> 9;
    const int t = threadIdx.x;

    __shared__ float qs[256];
    __shared__ int js[16];
    __shared__ float sc[16][8];
    __shared__ float wgt[16][8];

    if (t < 16) js[t] = pair_j[bi * 16 + t];
    qs[t] = q[(size_t)bi * DD + 256 + t];
    __syncthreads();

    if (t < 128) {
        const int d = t >> 3, h = t & 7;
        const int j = js[d];
        const float* kr = k + ((size_t)(b * NN + j)) * DD + 256 + h * 32;
        const float* er = ef + ((size_t)(bi * 16 + d)) * 256 + h * 32;
        const float* qr = qs + h * 32;
        float s = 0.f;
#pragma unroll
        for (int c4 = 0; c4 < 8; c4++) {
            float4 kk = *(const float4*)(kr + c4 * 4);
            float4 eee = *(const float4*)(er + c4 * 4);
            s = fmaf(qr[c4 * 4 + 0], kk.x * eee.x, s);
            s = fmaf(qr[c4 * 4 + 1], kk.y * eee.y, s);
            s = fmaf(qr[c4 * 4 + 2], kk.z * eee.z, s);
            s = fmaf(qr[c4 * 4 + 3], kk.w * eee.w, s);
        }
        sc[d][h] = s * SCALE;
    }
    __syncthreads();

    if (t < 8) {
        const int h = t;
        float m = -1e30f;
#pragma unroll
        for (int d = 0; d < 16; d++) {
            float s = sc[d][h];
            if (s > -10000.f && s > m) m = s;
        }
        float sum = 0.f;
#pragma unroll
        for (int d = 0; d < 16; d++) {
            float s = sc[d][h];
            float e = (s > -10000.f) ? expf(s - m) : 0.f;
            wgt[d][h] = e;
            sum += e;
        }
        float inv = (sum > 0.f) ? 1.f / sum : 0.f;
#pragma unroll
        for (int d = 0; d < 16; d++) wgt[d][h] *= inv;
    }
    __syncthreads();

    const int h = t >> 5, c = t & 31;
    float o = 0.f;
#pragma unroll
    for (int d = 0; d < 16; d++) {
        float w = wgt[d][h];
        o = fmaf(w, v[((size_t)(b * NN + js[d])) * DD + 256 + h * 32 + c], o);
    }
    ctx[(size_t)bi * DD + h * 64 + 32 + c] = __float2half_rn(o);
}

// ========== global attention: tensor-core flash kernel ==========
// grid (8 qtiles, 8 heads, 8 batch), 128 threads (4 warps x 16 q-rows).
// Scores: 3-term fp16 hi/lo split of Q and K (fp32-class accuracy, needed for top output).
// PV: P fp16 (softmax weights), V fp16 — same rounding class as fp16 ctx write.
__global__ __launch_bounds__(128) void global_attn_tc(
    const float* __restrict__ qf, const float* __restrict__ kf,
    const float* __restrict__ vf, const unsigned char* __restrict__ mask,
    __half* __restrict__ ctx, float* __restrict__ top)
{
    const int qt = blockIdx.x, h = blockIdx.y, b = blockIdx.z;
    const int t = threadIdx.x, lane = t & 31, w = t >> 5;

    __shared__ __half Qhi[64 * 40], Qlo[64 * 40];
    __shared__ __half Khi[64 * 40], Klo[64 * 40];
    __shared__ __half Vt[32 * 72];
    __shared__ unsigned char Ms[64 * 64];

    const uint32_t sQh = smem_to_u32(Qhi), sQl = smem_to_u32(Qlo);
    const uint32_t sKh = smem_to_u32(Khi), sKl = smem_to_u32(Klo);
    const uint32_t sV = smem_to_u32(Vt);

    // ---- Q tile load + hi/lo split (64 rows x 32 cols f32) ----
#pragma unroll
    for (int i = 0; i < 4; i++) {
        const int id = t + i * 128;             // 0..511
        const int row = id >> 3, ch = id & 7;   // ch: float4 chunk (4 floats)
        float4 v4 = *(const float4*)(qf + ((size_t)(b * NN) + qt * 64 + row) * DD + h * 32 + ch * 4);
        __half h0 = __float2half_rn(v4.x), h1 = __float2half_rn(v4.y);
        __half h2 = __float2half_rn(v4.z), h3 = __float2half_rn(v4.w);
        __half l0 = __float2half_rn(v4.x - __half2float(h0));
        __half l1 = __float2half_rn(v4.y - __half2float(h1));
        __half l2 = __float2half_rn(v4.z - __half2float(h2));
        __half l3 = __float2half_rn(v4.w - __half2float(h3));
        uint2 uh, ul;
        uh.x = ((uint32_t)__half_as_ushort(h1) << 16) | __half_as_ushort(h0);
        uh.y = ((uint32_t)__half_as_ushort(h3) << 16) | __half_as_ushort(h2);
        ul.x = ((uint32_t)__half_as_ushort(l1) << 16) | __half_as_ushort(l0);
        ul.y = ((uint32_t)__half_as_ushort(l3) << 16) | __half_as_ushort(l2);
        *(uint2*)&Qhi[row * 40 + ch * 4] = uh;
        *(uint2*)&Qlo[row * 40 + ch * 4] = ul;
    }

    const uint32_t aOff = (uint32_t)(w * 16 + (lane & 15)) * 80 + ((lane >> 4) << 4);
    const uint32_t bOffR = (uint32_t)((lane & 7) + ((lane >> 4) << 3));
    const uint32_t kOff = bOffR * 80 + (((lane >> 3) & 1) << 4);
    const uint32_t vOff = bOffR * 144 + (((lane >> 3) & 1) << 4);

    __syncthreads();
    uint32_t aHi[2][4], aLo[2][4];
    ldmx4(aHi[0], sQh + aOff);
    ldmx4(aHi[1], sQh + aOff + 32);
    ldmx4(aLo[0], sQl + aOff);
    ldmx4(aLo[1], sQl + aOff + 32);

    float o[4][4] = {};
    float mA = -1e30f, mB = -1e30f, lA = 0.f, lB = 0.f;
    const int rA = lane >> 2;
    const size_t qrow0 = (size_t)(b * NN) + qt * 64 + w * 16 + rA;

    for (int kt = 0; kt < 8; kt++) {
        __syncthreads();
        // K tile + split
#pragma unroll
        for (int i = 0; i < 4; i++) {
            const int id = t + i * 128;
            const int row = id >> 3, ch = id & 7;
            float4 v4 = *(const float4*)(kf + ((size_t)(b * NN) + kt * 64 + row) * DD + h * 32 + ch * 4);
            __half h0 = __float2half_rn(v4.x), h1 = __float2half_rn(v4.y);
            __half h2 = __float2half_rn(v4.z), h3 = __float2half_rn(v4.w);
            __half l0 = __float2half_rn(v4.x - __half2float(h0));
            __half l1 = __float2half_rn(v4.y - __half2float(h1));
            __half l2 = __float2half_rn(v4.z - __half2float(h2));
            __half l3 = __float2half_rn(v4.w - __half2float(h3));
            uint2 uh, ul;
            uh.x = ((uint32_t)__half_as_ushort(h1) << 16) | __half_as_ushort(h0);
            uh.y = ((uint32_t)__half_as_ushort(h3) << 16) | __half_as_ushort(h2);
            ul.x = ((uint32_t)__half_as_ushort(l1) << 16) | __half_as_ushort(l0);
            ul.y = ((uint32_t)__half_as_ushort(l3) << 16) | __half_as_ushort(l2);
            *(uint2*)&Khi[row * 40 + ch * 4] = uh;
            *(uint2*)&Klo[row * 40 + ch * 4] = ul;
        }
        // V tile: fp16 convert + transpose into Vt[dh][key]
#pragma unroll
        for (int i = 0; i < 4; i++) {
            const int id = t + i * 128;             // 0..511
            const int key = id >> 3, dh = (id & 7) * 4;
            float4 v4 = *(const float4*)(vf + ((size_t)(b * NN) + kt * 64 + key) * DD + h * 32 + dh);
            Vt[(dh + 0) * 72 + key] = __float2half_rn(v4.x);
            Vt[(dh + 1) * 72 + key] = __float2half_rn(v4.y);
            Vt[(dh + 2) * 72 + key] = __float2half_rn(v4.z);
            Vt[(dh + 3) * 72 + key] = __float2half_rn(v4.w);
        }
        // mask tile
#pragma unroll
        for (int i = 0; i < 2; i++) {
            const int id = t + i * 128;
            const int row = id >> 2, ch = id & 3;
            *(uint4*)&Ms[row * 64 + ch * 16] =
                *(const uint4*)(mask + ((size_t)(b * NN) + qt * 64 + row) * NN + kt * 64 + ch * 16);
        }
        __syncthreads();

        // ---- S = Q K^T (3-term) ----
        float s[8][4];
#pragma unroll
        for (int n = 0; n < 8; n++) { s[n][0] = s[n][1] = s[n][2] = s[n][3] = 0.f; }
#pragma unroll
        for (int ks = 0; ks < 2; ks++) {
#pragma unroll
            for (int jj = 0; jj < 4; jj++) {
                uint32_t bh[4], bl[4];
                ldmx4(bh, sKh + kOff + jj * (16 * 80) + ks * 32);
                ldmx4(bl, sKl + kOff + jj * (16 * 80) + ks * 32);
                mma16816(s[jj * 2],     aHi[ks], bh[0], bh[1]);
                mma16816(s[jj * 2 + 1], aHi[ks], bh[2], bh[3]);
                mma16816(s[jj * 2],     aHi[ks], bl[0], bl[1]);
                mma16816(s[jj * 2 + 1], aHi[ks], bl[2], bl[3]);
                mma16816(s[jj * 2],     aLo[ks], bh[0], bh[1]);
                mma16816(s[jj * 2 + 1], aLo[ks], bh[2], bh[3]);
            }
        }
#pragma unroll
        for (int n = 0; n < 8; n++) {
            s[n][0] *= SCALE; s[n][1] *= SCALE; s[n][2] *= SCALE; s[n][3] *= SCALE;
        }

        // top (pre-mask) for h==0
        if (h == 0) {
#pragma unroll
            for (int n = 0; n < 8; n++) {
                const int col = kt * 64 + n * 8 + (lane & 3) * 2;
                *(float2*)(top + qrow0 * NN + col) = make_float2(s[n][0], s[n][1]);
                *(float2*)(top + (qrow0 + 8) * NN + col) = make_float2(s[n][2], s[n][3]);
            }
        }
        // mask
        {
            const int lr = w * 16 + rA;
#pragma unroll
            for (int n = 0; n < 8; n++) {
                const int col = n * 8 + (lane & 3) * 2;
                if (Ms[lr * 64 + col])           s[n][0] = -1e18f;
                if (Ms[lr * 64 + col + 1])       s[n][1] = -1e18f;
                if (Ms[(lr + 8) * 64 + col])     s[n][2] = -1e18f;
                if (Ms[(lr + 8) * 64 + col + 1]) s[n][3] = -1e18f;
            }
        }

        // ---- online softmax ----
        float tmA = -1e30f, tmB = -1e30f;
#pragma unroll
        for (int n = 0; n < 8; n++) {
            tmA = fmaxf(tmA, fmaxf(s[n][0], s[n][1]));
            tmB = fmaxf(tmB, fmaxf(s[n][2], s[n][3]));
        }
        tmA = fmaxf(tmA, __shfl_xor_sync(0xffffffffu, tmA, 1));
        tmA = fmaxf(tmA, __shfl_xor_sync(0xffffffffu, tmA, 2));
        tmB = fmaxf(tmB, __shfl_xor_sync(0xffffffffu, tmB, 1));
        tmB = fmaxf(tmB, __shfl_xor_sync(0xffffffffu, tmB, 2));
        const float mAn = fmaxf(mA, tmA), mBn = fmaxf(mB, tmB);
        const float fAc = __expf(mA - mAn), fBc = __expf(mB - mBn);
        float sumA = 0.f, sumB = 0.f;
        uint32_t pf[4][4];
#pragma unroll
        for (int n = 0; n < 8; n++) {
            float p0 = __expf(s[n][0] - mAn), p1 = __expf(s[n][1] - mAn);
            float p2 = __expf(s[n][2] - mBn), p3 = __expf(s[n][3] - mBn);
            sumA += p0 + p1; sumB += p2 + p3;
            pf[n >> 1][(n & 1) * 2]     = packh2(p0, p1);
            pf[n >> 1][(n & 1) * 2 + 1] = packh2(p2, p3);
        }
        sumA += __shfl_xor_sync(0xffffffffu, sumA, 1);
        sumA += __shfl_xor_sync(0xffffffffu, sumA, 2);
        sumB += __shfl_xor_sync(0xffffffffu, sumB, 1);
        sumB += __shfl_xor_sync(0xffffffffu, sumB, 2);
        lA = lA * fAc + sumA;
        lB = lB * fBc + sumB;
#pragma unroll
        for (int n = 0; n < 4; n++) {
            o[n][0] *= fAc; o[n][1] *= fAc; o[n][2] *= fBc; o[n][3] *= fBc;
        }
        mA = mAn; mB = mBn;

        // ---- O += P V ----
#pragma unroll
        for (int kfi = 0; kfi < 4; kfi++) {
#pragma unroll
            for (int jj = 0; jj < 2; jj++) {
                uint32_t bv[4];
                ldmx4(bv, sV + vOff + jj * (16 * 144) + kfi * 32);
                mma16816(o[jj * 2],     pf[kfi], bv[0], bv[1]);
                mma16816(o[jj * 2 + 1], pf[kfi], bv[2], bv[3]);
            }
        }
    }

    // epilogue
    const float iA = 1.f / lA, iB = 1.f / lB;
#pragma unroll
    for (int n = 0; n < 4; n++) {
        const int col = h * 64 + n * 8 + (lane & 3) * 2;
        *(uint32_t*)(ctx + qrow0 * DD + col) = packh2(o[n][0] * iA, o[n][1] * iA);
        *(uint32_t*)(ctx + (qrow0 + 8) * DD + col) = packh2(o[n][2] * iB, o[n][3] * iB);
    }
}

// ---------------- eu: one block per (b,i); P row in regs, 16 edges ----------------
__global__ __launch_bounds__(128) void eu_kernel(
    const float* __restrict__ PQ,
    const int* __restrict__ pair_j,
    __half* __restrict__ eu)
{
    const int bi = blockIdx.x;          // b*N + i
    const int b = bi >> 9;
    const int t = threadIdx.x;          // 0..127 -> 4 floats each

    __shared__ int js[16];
    if (t < 16) js[t] = pair_j[bi * 16 + t];

    const float4 p = *(const float4*)(PQ + (size_t)bi * 1024 + t * 4);
    __syncthreads();

#pragma unroll 4
    for (int d = 0; d < 16; d++) {
        const int j = js[d];
        float4 c = *(const float4*)(PQ + ((size_t)(b * NN + j)) * 1024 + 512 + t * 4);
        float r0 = softplusf(p.x + c.x) - LOG2F_;
        float r1 = softplusf(p.y + c.y) - LOG2F_;
        float r2 = softplusf(p.z + c.z) - LOG2F_;
        float r3 = softplusf(p.w + c.w) - LOG2F_;
        uint2 u;
        u.x = packh2(r0, r1);
        u.y = packh2(r2, r3);
        *(uint2*)(eu + ((size_t)(bi * 16 + d)) * DD + t * 4) = u;
    }
}

// ---------------- launch ----------------
extern "C" void kernel_launch(void* const* d_in, const int* in_sizes, int n_in,
                              void* d_out, int out_size)
{
    const float* key    = (const float*)d_in[0];
    const float* value  = (const float*)d_in[1];
    const float* query  = (const float*)d_in[2];
    const unsigned char* mask = (const unsigned char*)d_in[3];
    const float* edgef  = (const float*)d_in[4];
    const int* pair_b   = (const int*)d_in[5];
    const int* pair_i   = (const int*)d_in[6];
    const int* pair_j   = (const int*)d_in[7];
    const float* Wq = (const float*)d_in[8],  *bq = (const float*)d_in[9];
    const float* Wk = (const float*)d_in[10], *bk = (const float*)d_in[11];
    const float* Wv = (const float*)d_in[12], *bv = (const float*)d_in[13];
    const float* Wo = (const float*)d_in[14], *bo = (const float*)d_in[15];
    const float* We1 = (const float*)d_in[16], *be1 = (const float*)d_in[17];
    const float* We2 = (const float*)d_in[18], *be2 = (const float*)d_in[19];
    const float* Wu1 = (const float*)d_in[20], *bu1 = (const float*)d_in[21];
    const float* Wu2 = (const float*)d_in[22], *bu2 = (const float*)d_in[23];

    float* out  = (float*)d_out;
    float* top  = out + 2097152;
    float* eupd = out + 4194304;

    float *q_, *k_, *v_, *PQ_, *ef_, *biasPQ_;
    __half *eF_, *f1_, *eu_, *xK_, *xQ_, *xV_, *xC_, *o_, *WHi_;
    cudaGetSymbolAddress((void**)&q_, g_q);
    cudaGetSymbolAddress((void**)&k_, g_k);
    cudaGetSymbolAddress((void**)&v_, g_v);
    cudaGetSymbolAddress((void**)&PQ_, g_PQ);
    cudaGetSymbolAddress((void**)&ef_, g_ef);
    cudaGetSymbolAddress((void**)&eF_, g_eF);
    cudaGetSymbolAddress((void**)&f1_, g_f1);
    cudaGetSymbolAddress((void**)&eu_, g_eu);
    cudaGetSymbolAddress((void**)&xK_, g_xK);
    cudaGetSymbolAddress((void**)&xQ_, g_xQ);
    cudaGetSymbolAddress((void**)&xV_, g_xV);
    cudaGetSymbolAddress((void**)&xC_, g_xC);
    cudaGetSymbolAddress((void**)&o_, g_o);
    cudaGetSymbolAddress((void**)&WHi_, g_WHi);
    cudaGetSymbolAddress((void**)&biasPQ_, g_biasPQ);

    cudaFuncSetAttribute((const void*)tc_gemm<0, 0>,
                         cudaFuncAttributeMaxDynamicSharedMemorySize, TC_SMEM);
    cudaFuncSetAttribute((const void*)tc_gemm<1, 1>,
                         cudaFuncAttributeMaxDynamicSharedMemorySize, TC_SMEM);
    cudaFuncSetAttribute((const void*)tc_gemm<0, 2>,
                         cudaFuncAttributeMaxDynamicSharedMemorySize, TC_SMEM);

    const int WSZ = 262144;

    // all weight prep in one launch
    wsplit_all<<<8708, 256>>>(Wk, Wq, Wv, Wo, Wu1, Wu2, We1, We2, bu1,
                              WHi_, biasPQ_);

    // input conversions
    conv_f16<<<32768, 256>>>(edgef, eF_, (size_t)EE * DD / 4);
    conv3_f16<<<6144, 256>>>(key, query, value, xK_, xQ_, xV_);

    // edge feature MLP (tensor cores)
    tc_gemm<1, 1><<<dim3(4, 512), 256, TC_SMEM>>>(eF_, WHi_ + 7 * WSZ,
                                                  be1, nullptr, f1_, 512);
    tc_gemm<0, 0><<<dim3(2, 512), 256, TC_SMEM>>>(f1_, WHi_ + 8 * WSZ,
                                                  be2, ef_, nullptr, 256);

    // projections
    tc_gemm<0, 0><<<dim3(4, 32), 256, TC_SMEM>>>(xK_, WHi_ + 0 * WSZ,
                                                 bk, k_, nullptr, 512);
    tc_gemm<0, 0><<<dim3(4, 32), 256, TC_SMEM>>>(xQ_, WHi_ + 1 * WSZ,
                                                 bq, q_, nullptr, 512);
    tc_gemm<0, 0><<<dim3(4, 32), 256, TC_SMEM>>>(xV_, WHi_ + 2 * WSZ,
                                                 bv, v_, nullptr, 512);

    // attention -> ctx (fp16 direct)
    local_attn<<<ROWS, 256>>>(q_, k_, v_, ef_, pair_j, xC_);
    global_attn_tc<<<dim3(8, 8, 8), 128>>>(q_, k_, v_, mask, xC_, top);

    // output projection (emit f32 out + fp16 o for downstream)
    tc_gemm<0, 2><<<dim3(4, 32), 256, TC_SMEM>>>(xC_, WHi_ + 3 * WSZ,
                                                 bo, out, o_, 512);

    // P,Q in one GEMM over stacked Wu1 halves (N=1024)
    tc_gemm<0, 0><<<dim3(8, 32), 256, TC_SMEM>>>(o_, WHi_ + 4 * WSZ,
                                                 biasPQ_, PQ_, nullptr, 1024);

    // eu = softplus(P_i + Q_j) - log2 -> fp16
    eu_kernel<<<ROWS, 128>>>(PQ_, pair_j, eu_);

    // edge_updated = eu @ Wu2 + bu2
    tc_gemm<0, 0><<<dim3(4, 512), 256, TC_SMEM>>>(eu_, WHi_ + 6 * WSZ,
                                                  bu2, eupd, nullptr, 512);
}